// round 2
// baseline (speedup 1.0000x reference)
#include <cuda_runtime.h>
#include <cuda_bf16.h>
#include <math.h>

// Problem constants
#define NXX   729
#define NEQX  300
#define BAT   16
#define LDSM  304                 // leading dim of S (row-major, padded)
#define SSTR  (NEQX*LDSM)         // 91200 floats per batch S matrix
#define NPAN  10                  // ceil(300/32) panels
#define SIGC  0.1f
#define BIGV  1e9f

// ---------------- device scratch (no allocations allowed) ----------------
__device__ float g_P   [BAT*NXX];
__device__ float g_Z   [BAT*NXX];
__device__ float g_Sl  [BAT*NXX];   // slack s
__device__ float g_Lm  [BAT*NXX];   // lam
__device__ float g_Qt  [BAT*NXX];   // q = A^T nu
__device__ float g_HINV[BAT*NXX];
__device__ float g_R1  [BAT*NXX];
__device__ float g_RP  [BAT*NXX];
__device__ float g_RS  [BAT*NXX];
__device__ float g_NU  [BAT*NEQX];
__device__ float g_DNU [BAT*NEQX];
__device__ float g_RHS [BAT*NEQX];
__device__ float g_Smat[BAT*SSTR];  // per-batch Schur complements / factors
__device__ float g_S0  [SSTR];      // init Schur complement (batch-independent)
__device__ float g_Qd  [NXX];
__device__ float g_Hinv0[NXX];

// ---------------- reductions ----------------
__device__ __forceinline__ float blkSum(float v, float* red) {
    #pragma unroll
    for (int o = 16; o; o >>= 1) v += __shfl_xor_sync(0xffffffffu, v, o);
    int w = threadIdx.x >> 5;
    if ((threadIdx.x & 31) == 0) red[w] = v;
    __syncthreads();
    if (threadIdx.x < 32) {
        int nw = blockDim.x >> 5;
        v = (threadIdx.x < nw) ? red[threadIdx.x] : 0.f;
        #pragma unroll
        for (int o = 16; o; o >>= 1) v += __shfl_xor_sync(0xffffffffu, v, o);
        if (threadIdx.x == 0) red[0] = v;
    }
    __syncthreads();
    return red[0];
}

__device__ __forceinline__ float blkMin(float v, float* red) {
    #pragma unroll
    for (int o = 16; o; o >>= 1) v = fminf(v, __shfl_xor_sync(0xffffffffu, v, o));
    int w = threadIdx.x >> 5;
    if ((threadIdx.x & 31) == 0) red[w] = v;
    __syncthreads();
    if (threadIdx.x < 32) {
        int nw = blockDim.x >> 5;
        v = (threadIdx.x < nw) ? red[threadIdx.x] : BIGV;
        #pragma unroll
        for (int o = 16; o; o >>= 1) v = fminf(v, __shfl_xor_sync(0xffffffffu, v, o));
        if (threadIdx.x == 0) red[0] = v;
    }
    __syncthreads();
    return red[0];
}

// ---------------- setup: p = -puzzles, Qd, Hinv0 ----------------
__global__ void k_setup(const float* __restrict__ puz, const float* __restrict__ Q) {
    int b = blockIdx.x, i = threadIdx.x;
    if (i < NXX) {
        g_P[b*NXX + i] = -puz[b*NXX + i];
        if (b == 0) {
            float qd = Q[i*NXX + i];
            g_Qd[i] = qd;
            g_Hinv0[i] = 1.0f / qd;
        }
    }
}

// ---------------- batched SYRK: S = A diag(Hinv) A^T (lower triangle) ------
// 64x64 tiles, K-chunks of 32, 256 threads, 4x4 microtile per thread.
__global__ void __launch_bounds__(256) k_syrk(const float* __restrict__ A, int init) {
    int t = blockIdx.x, b = blockIdx.y;
    int ti = 0;
    while ((ti + 1) * (ti + 2) / 2 <= t) ti++;
    int tj = t - ti * (ti + 1) / 2;
    const float* hv = init ? g_Hinv0 : (g_HINV + b*NXX);
    float* Sout     = init ? g_S0    : (g_Smat + b*SSTR);

    __shared__ __align__(16) float As[32*68];
    __shared__ __align__(16) float Bs[32*68];

    int tid = threadIdx.x;
    int tx = tid & 15, ty = tid >> 4;
    float acc[4][4];
    #pragma unroll
    for (int u = 0; u < 4; u++)
        #pragma unroll
        for (int v = 0; v < 4; v++) acc[u][v] = 0.f;

    int row0 = ti * 64, col0 = tj * 64;
    int cld = tid & 31, rbase = tid >> 5;

    for (int k0 = 0; k0 < NXX; k0 += 32) {
        int k = k0 + cld;
        bool kok = (k < NXX);
        float hval = kok ? hv[k] : 0.f;
        #pragma unroll
        for (int l = 0; l < 8; l++) {
            int r = rbase + l * 8;
            int gi = row0 + r;
            int gj = col0 + r;
            float av = (kok && gi < NEQX) ? A[gi*NXX + k] : 0.f;
            float bv = (kok && gj < NEQX) ? A[gj*NXX + k] : 0.f;
            As[cld*68 + r] = av * hval;
            Bs[cld*68 + r] = bv;
        }
        __syncthreads();
        #pragma unroll
        for (int kk = 0; kk < 32; kk++) {
            float4 a4 = *reinterpret_cast<const float4*>(&As[kk*68 + (ty << 2)]);
            float4 b4 = *reinterpret_cast<const float4*>(&Bs[kk*68 + (tx << 2)]);
            float av[4] = {a4.x, a4.y, a4.z, a4.w};
            float bv[4] = {b4.x, b4.y, b4.z, b4.w};
            #pragma unroll
            for (int u = 0; u < 4; u++)
                #pragma unroll
                for (int v = 0; v < 4; v++) acc[u][v] += av[u] * bv[v];
        }
        __syncthreads();
    }
    #pragma unroll
    for (int u = 0; u < 4; u++) {
        int gi = row0 + (ty << 2) + u;
        #pragma unroll
        for (int v = 0; v < 4; v++) {
            int gj = col0 + (tx << 2) + v;
            if (gi < NEQX && gj < NEQX && gj <= gi)
                Sout[gi*LDSM + gj] = acc[u][v];
        }
    }
}

// ---------------- blocked left-looking Cholesky (one CTA per batch) -------
// Factor stored in lower triangle; mirrored into upper triangle (for
// coalesced reads in the update phase and in the triangular solves).
__global__ void __launch_bounds__(320) k_chol(int init) {
    float* S = init ? g_S0 : (g_Smat + blockIdx.x*SSTR);
    __shared__ float sp[300*33];   // panel: 300 rows x 32 (+1 pad)
    __shared__ float stp[32*32];
    __shared__ float sinvd[32];
    int tid = threadIdx.x;

    for (int p = 0; p < NPAN; p++) {
        int col0 = p * 32;
        int pw = NEQX - col0; if (pw > 32) pw = 32;
        int nrows = NEQX - col0;
        // load panel (rows [col0,300), cols [col0,col0+pw))
        for (int idx = tid; idx < nrows * 32; idx += 320) {
            int r = idx >> 5, c = idx & 31;
            sp[r*33 + c] = (c < pw) ? S[(col0 + r)*LDSM + col0 + c] : 0.f;
        }
        __syncthreads();

        int r = tid;
        bool act = (r < nrows);
        int grow = col0 + r;

        if (col0 > 0) {
            float accu[32];
            #pragma unroll
            for (int c = 0; c < 32; c++) accu[c] = 0.f;
            for (int k0 = 0; k0 < col0; k0 += 32) {
                for (int idx = tid; idx < 1024; idx += 320) {
                    int kk = idx >> 5, c = idx & 31;
                    int gc = col0 + c;
                    stp[idx] = (gc < NEQX) ? S[(k0 + kk)*LDSM + gc] : 0.f; // mirror row: L[gc][k0+kk]
                }
                __syncthreads();
                if (act) {
                    #pragma unroll 4
                    for (int kk = 0; kk < 32; kk++) {
                        float mval = S[(k0 + kk)*LDSM + grow];  // mirror: L[grow][k0+kk], coalesced
                        #pragma unroll
                        for (int c = 0; c < 32; c++) accu[c] += mval * stp[kk*32 + c];
                    }
                }
                __syncthreads();
            }
            if (act) {
                #pragma unroll
                for (int c = 0; c < 32; c++) sp[r*33 + c] -= accu[c];
            }
            __syncthreads();
        }

        // factor pw x pw diagonal block (warp 0, warp-synchronous in smem)
        if (tid < 32) {
            int lane = tid;
            for (int c = 0; c < pw; c++) {
                float dval = sp[c*33 + c];
                __syncwarp();
                float d = sqrtf(dval);
                float invd = 1.0f / d;
                if (lane == 0) { sp[c*33 + c] = d; sinvd[c] = invd; }
                if (lane > c && lane < pw) sp[lane*33 + c] *= invd;
                __syncwarp();
                if (lane > c && lane < pw) {
                    float lic = sp[lane*33 + c];
                    for (int j = c + 1; j <= lane; j++)
                        sp[lane*33 + j] -= lic * sp[j*33 + c];
                }
                __syncwarp();
            }
        }
        __syncthreads();

        // rows below diagonal block: per-thread serial triangular solve
        if (act && r >= pw) {
            float lr[32];
            #pragma unroll
            for (int c = 0; c < 32; c++) {
                if (c < pw) {
                    float v = sp[r*33 + c];
                    #pragma unroll
                    for (int j = 0; j < 32; j++)
                        if (j < c) v -= lr[j] * sp[c*33 + j];
                    v *= sinvd[c];
                    lr[c] = v;
                    sp[r*33 + c] = v;
                }
            }
        }
        __syncthreads();

        // store panel: lower + mirrored upper
        for (int idx = tid; idx < nrows * 32; idx += 320) {
            int r2 = idx >> 5, c = idx & 31;
            if (c < pw && r2 >= c) {
                float v = sp[r2*33 + c];
                S[(col0 + r2)*LDSM + col0 + c] = v;
                S[(col0 + c)*LDSM + col0 + r2] = v;
            }
        }
        __syncthreads();
    }
}

// ---------------- triangular solves L L^T x = rhs (one CTA per batch) -----
__global__ void __launch_bounds__(320) k_trsolve(int init) {
    int b = blockIdx.x;
    const float* S   = init ? g_S0 : (g_Smat + b*SSTR);
    const float* rhs = g_RHS + b*NEQX;
    float* out       = init ? (g_NU + b*NEQX) : (g_DNU + b*NEQX);
    __shared__ float sy[NEQX];
    __shared__ float db[32*33];
    int tid = threadIdx.x;
    int lane = tid & 31;
    if (tid < NEQX) sy[tid] = rhs[tid];
    __syncthreads();

    // forward: L y = rhs
    for (int p = 0; p < NPAN; p++) {
        int col0 = p * 32;
        int pw = NEQX - col0; if (pw > 32) pw = 32;
        for (int idx = tid; idx < 1024; idx += 320) {
            int i = idx >> 5, j = idx & 31;
            db[i*33 + j] = (col0 + i < NEQX && col0 + j < NEQX)
                           ? S[(col0 + i)*LDSM + col0 + j] : 0.f;
        }
        __syncthreads();
        if (tid < 32) {
            for (int c = 0; c < pw; c++) {
                float contrib = (lane < c) ? db[c*33 + lane] * sy[col0 + lane] : 0.f;
                #pragma unroll
                for (int o = 16; o; o >>= 1) contrib += __shfl_xor_sync(0xffffffffu, contrib, o);
                if (lane == 0) sy[col0 + c] = (sy[col0 + c] - contrib) / db[c*33 + c];
                __syncwarp();
            }
        }
        __syncthreads();
        int rem = NEQX - col0 - pw;
        if (tid < rem) {
            int i = col0 + pw + tid;
            float s = 0.f;
            #pragma unroll 4
            for (int c = 0; c < pw; c++) s += S[(col0 + c)*LDSM + i] * sy[col0 + c]; // mirror, coalesced
            sy[i] -= s;
        }
        __syncthreads();
    }
    // backward: L^T x = y
    for (int p = NPAN - 1; p >= 0; p--) {
        int col0 = p * 32;
        int pw = NEQX - col0; if (pw > 32) pw = 32;
        for (int idx = tid; idx < 1024; idx += 320) {
            int i = idx >> 5, j = idx & 31;
            db[i*33 + j] = (col0 + i < NEQX && col0 + j < NEQX)
                           ? S[(col0 + i)*LDSM + col0 + j] : 0.f;
        }
        __syncthreads();
        if (tid < 32) {
            for (int c = pw - 1; c >= 0; c--) {
                float contrib = (lane > c && lane < pw) ? db[lane*33 + c] * sy[col0 + lane] : 0.f;
                #pragma unroll
                for (int o = 16; o; o >>= 1) contrib += __shfl_xor_sync(0xffffffffu, contrib, o);
                if (lane == 0) sy[col0 + c] = (sy[col0 + c] - contrib) / db[c*33 + c];
                __syncwarp();
            }
        }
        __syncthreads();
        if (tid < col0) {
            float s = 0.f;
            #pragma unroll 4
            for (int c = 0; c < pw; c++) s += S[(col0 + c)*LDSM + tid] * sy[col0 + c]; // lower row, coalesced
            sy[tid] -= s;
        }
        __syncthreads();
    }
    if (tid < NEQX) out[tid] = sy[tid];
}

// ---------------- init rhs: -A (p*Hinv0) - b ----------------
__global__ void __launch_bounds__(768) k_rhs0(const float* __restrict__ A, const float* __restrict__ bv) {
    int b = blockIdx.x, tid = threadIdx.x;
    __shared__ float su[NXX];
    if (tid < NXX) su[tid] = g_P[b*NXX + tid] * g_Hinv0[tid];
    __syncthreads();
    int w = tid >> 5, lane = tid & 31;
    for (int j = w; j < NEQX; j += 24) {
        float s = 0.f;
        for (int k = lane; k < NXX; k += 32) s += A[j*NXX + k] * su[k];
        #pragma unroll
        for (int o = 16; o; o >>= 1) s += __shfl_xor_sync(0xffffffffu, s, o);
        if (lane == 0) g_RHS[b*NEQX + j] = -s - bv[j];
    }
}

// ---------------- init z, s, lam, q ----------------
__global__ void __launch_bounds__(768) k_initz(const float* __restrict__ A, const float* __restrict__ h) {
    int b = blockIdx.x, tid = threadIdx.x;
    __shared__ float snu[NEQX];
    if (tid < NEQX) snu[tid] = g_NU[b*NEQX + tid];
    __syncthreads();
    if (tid < NXX) {
        float q = 0.f;
        #pragma unroll 4
        for (int j = 0; j < NEQX; j++) q += A[j*NXX + tid] * snu[j];
        float z = (-g_P[b*NXX + tid] - q) * g_Hinv0[tid];
        float s = fmaxf(h[tid] + z, 1.0f);    // h - G z with G = -I
        g_Qt[b*NXX + tid] = q;
        g_Z [b*NXX + tid] = z;
        g_Sl[b*NXX + tid] = s;
        g_Lm[b*NXX + tid] = 1.0f;
    }
}

// ---------------- per-iteration residuals + dnu RHS ----------------
__global__ void __launch_bounds__(768) k_res(const float* __restrict__ A,
                                             const float* __restrict__ bv,
                                             const float* __restrict__ h) {
    int b = blockIdx.x, tid = threadIdx.x;
    __shared__ float su[NXX];
    __shared__ float red[32];
    float si = 0.f, li = 0.f, part = 0.f;
    if (tid < NXX) {
        si = g_Sl[b*NXX + tid];
        li = g_Lm[b*NXX + tid];
        part = si * li;
    }
    float mu = blkSum(part, red) * (1.0f / (float)NXX);
    if (tid < NXX) {
        float zi = g_Z[b*NXX + tid];
        float pi = g_P[b*NXX + tid];
        float qi = g_Qt[b*NXX + tid];
        float qd = g_Qd[tid];
        float hi = h[tid];
        float rz = qd*zi + pi - li + qi;            // G^T lam = -lam
        float rp = si - zi - hi;                    // G z + s - h
        float rs = si*li - SIGC*mu;
        float hd = qd + li/si;
        float hinv = 1.0f/hd;
        float r1 = -rz + (li*rp - rs)/si;           // -rz - G^T((lam rp - rs)/s)
        g_HINV[b*NXX + tid] = hinv;
        g_R1 [b*NXX + tid] = r1;
        g_RP [b*NXX + tid] = rp;
        g_RS [b*NXX + tid] = rs;
        su[tid] = r1*hinv + zi;                     // w + z ; A(w+z)-b = A w + re
    }
    __syncthreads();
    int w = tid >> 5, lane = tid & 31;
    for (int j = w; j < NEQX; j += 24) {
        float s = 0.f;
        for (int k = lane; k < NXX; k += 32) s += A[j*NXX + k] * su[k];
        #pragma unroll
        for (int o = 16; o; o >>= 1) s += __shfl_xor_sync(0xffffffffu, s, o);
        if (lane == 0) g_RHS[b*NEQX + j] = s - bv[j];
    }
}

// ---------------- step: dz/ds/dlam, alpha, updates ----------------
__global__ void __launch_bounds__(768) k_step(const float* __restrict__ A) {
    int b = blockIdx.x, tid = threadIdx.x;
    __shared__ float sdnu[NEQX];
    __shared__ float red[32];
    if (tid < NEQX) sdnu[tid] = g_DNU[b*NEQX + tid];
    __syncthreads();
    float cand = BIGV;
    float t = 0.f, dz = 0.f, ds = 0.f, dlam = 0.f, si = 0.f, li = 0.f;
    if (tid < NXX) {
        #pragma unroll 4
        for (int j = 0; j < NEQX; j++) t += A[j*NXX + tid] * sdnu[j];
        float r1   = g_R1 [b*NXX + tid];
        float hinv = g_HINV[b*NXX + tid];
        float rp   = g_RP [b*NXX + tid];
        float rs   = g_RS [b*NXX + tid];
        si = g_Sl[b*NXX + tid];
        li = g_Lm[b*NXX + tid];
        dz = (r1 - t) * hinv;
        ds = dz - rp;                         // -rp - G dz
        dlam = (-rs - li*ds) / si;
        if (ds   < 0.f) cand = fminf(cand, -si/ds);
        if (dlam < 0.f) cand = fminf(cand, -li/dlam);
    }
    float am = blkMin(cand, red);
    float alpha = fminf(1.0f, 0.99f * am);
    if (tid < NXX) {
        g_Z [b*NXX + tid] += alpha * dz;
        g_Sl[b*NXX + tid]  = si + alpha * ds;
        g_Lm[b*NXX + tid]  = li + alpha * dlam;
        g_Qt[b*NXX + tid] += alpha * t;       // q = A^T nu incrementally
    }
    if (tid < NEQX) g_NU[b*NEQX + tid] += alpha * sdnu[tid];
}

// ---------------- output copy ----------------
__global__ void k_out(float* __restrict__ out) {
    int b = blockIdx.x, i = threadIdx.x;
    if (i < NXX) out[b*NXX + i] = g_Z[b*NXX + i];
}

// ---------------- launch ----------------
extern "C" void kernel_launch(void* const* d_in, const int* in_sizes, int n_in,
                              void* d_out, int out_size) {
    const float* puzzles = (const float*)d_in[0];
    const float* Q       = (const float*)d_in[1];
    // d_in[2] is G = -I (exploited analytically)
    const float* h       = (const float*)d_in[3];
    const float* A       = (const float*)d_in[4];
    const float* bvec    = (const float*)d_in[5];
    float* out = (float*)d_out;

    // init
    k_setup  <<<BAT, 768>>>(puzzles, Q);
    k_syrk   <<<dim3(15, 1), 256>>>(A, 1);
    k_chol   <<<1, 320>>>(1);
    k_rhs0   <<<BAT, 768>>>(A, bvec);
    k_trsolve<<<BAT, 320>>>(1);
    k_initz  <<<BAT, 768>>>(A, h);

    // 10 PDIPM iterations
    for (int it = 0; it < 10; it++) {
        k_res    <<<BAT, 768>>>(A, bvec, h);
        k_syrk   <<<dim3(15, BAT), 256>>>(A, 0);
        k_chol   <<<BAT, 320>>>(0);
        k_trsolve<<<BAT, 320>>>(0);
        k_step   <<<BAT, 768>>>(A);
    }
    k_out<<<BAT, 768>>>(out);
}

// round 3
// speedup vs baseline: 1.8296x; 1.8296x over previous
#include <cuda_runtime.h>
#include <cuda_bf16.h>
#include <math.h>

// Problem constants
#define NXX   729
#define NEQX  300
#define BAT   16
#define LDSM  304                 // leading dim of S (row-major, padded)
#define SSTR  (NEQX*LDSM)         // 91200 floats per batch S matrix
#define NPAN  10                  // ceil(300/32) panels
#define SIGC  0.1f
#define BIGV  1e9f

// ---------------- device scratch (no allocations allowed) ----------------
__device__ float g_P   [BAT*NXX];
__device__ float g_Z   [BAT*NXX];
__device__ float g_Sl  [BAT*NXX];   // slack s
__device__ float g_Lm  [BAT*NXX];   // lam
__device__ float g_Qt  [BAT*NXX];   // q = A^T nu
__device__ float g_HINV[BAT*NXX];
__device__ float g_R1  [BAT*NXX];
__device__ float g_RP  [BAT*NXX];
__device__ float g_RS  [BAT*NXX];
__device__ float g_NU  [BAT*NEQX];
__device__ float g_DNU [BAT*NEQX];
__device__ float g_RHS [BAT*NEQX];
__device__ float g_Smat[BAT*SSTR];  // per-batch Schur complements / factors
__device__ float g_S0  [SSTR];      // init Schur complement (batch-independent)
__device__ float g_Qd  [NXX];
__device__ float g_Hinv0[NXX];

// ---------------- reductions ----------------
__device__ __forceinline__ float blkSum(float v, float* red) {
    #pragma unroll
    for (int o = 16; o; o >>= 1) v += __shfl_xor_sync(0xffffffffu, v, o);
    int w = threadIdx.x >> 5;
    if ((threadIdx.x & 31) == 0) red[w] = v;
    __syncthreads();
    if (threadIdx.x < 32) {
        int nw = blockDim.x >> 5;
        v = (threadIdx.x < nw) ? red[threadIdx.x] : 0.f;
        #pragma unroll
        for (int o = 16; o; o >>= 1) v += __shfl_xor_sync(0xffffffffu, v, o);
        if (threadIdx.x == 0) red[0] = v;
    }
    __syncthreads();
    return red[0];
}

__device__ __forceinline__ float blkMin(float v, float* red) {
    #pragma unroll
    for (int o = 16; o; o >>= 1) v = fminf(v, __shfl_xor_sync(0xffffffffu, v, o));
    int w = threadIdx.x >> 5;
    if ((threadIdx.x & 31) == 0) red[w] = v;
    __syncthreads();
    if (threadIdx.x < 32) {
        int nw = blockDim.x >> 5;
        v = (threadIdx.x < nw) ? red[threadIdx.x] : BIGV;
        #pragma unroll
        for (int o = 16; o; o >>= 1) v = fminf(v, __shfl_xor_sync(0xffffffffu, v, o));
        if (threadIdx.x == 0) red[0] = v;
    }
    __syncthreads();
    return red[0];
}

// ---------------- setup: p = -puzzles, Qd, Hinv0 ----------------
__global__ void k_setup(const float* __restrict__ puz, const float* __restrict__ Q) {
    int b = blockIdx.x, i = threadIdx.x;
    if (i < NXX) {
        g_P[b*NXX + i] = -puz[b*NXX + i];
        if (b == 0) {
            float qd = Q[i*NXX + i];
            g_Qd[i] = qd;
            g_Hinv0[i] = 1.0f / qd;
        }
    }
}

// ---------------- batched SYRK: S = A diag(Hinv) A^T (lower triangle) ------
__global__ void __launch_bounds__(256) k_syrk(const float* __restrict__ A, int init) {
    int t = blockIdx.x, b = blockIdx.y;
    int ti = 0;
    while ((ti + 1) * (ti + 2) / 2 <= t) ti++;
    int tj = t - ti * (ti + 1) / 2;
    const float* hv = init ? g_Hinv0 : (g_HINV + b*NXX);
    float* Sout     = init ? g_S0    : (g_Smat + b*SSTR);

    __shared__ __align__(16) float As[32*68];
    __shared__ __align__(16) float Bs[32*68];

    int tid = threadIdx.x;
    int tx = tid & 15, ty = tid >> 4;
    float acc[4][4];
    #pragma unroll
    for (int u = 0; u < 4; u++)
        #pragma unroll
        for (int v = 0; v < 4; v++) acc[u][v] = 0.f;

    int row0 = ti * 64, col0 = tj * 64;
    int cld = tid & 31, rbase = tid >> 5;

    for (int k0 = 0; k0 < NXX; k0 += 32) {
        int k = k0 + cld;
        bool kok = (k < NXX);
        float hval = kok ? hv[k] : 0.f;
        #pragma unroll
        for (int l = 0; l < 8; l++) {
            int r = rbase + l * 8;
            int gi = row0 + r;
            int gj = col0 + r;
            float av = (kok && gi < NEQX) ? A[gi*NXX + k] : 0.f;
            float bv = (kok && gj < NEQX) ? A[gj*NXX + k] : 0.f;
            As[cld*68 + r] = av * hval;
            Bs[cld*68 + r] = bv;
        }
        __syncthreads();
        #pragma unroll
        for (int kk = 0; kk < 32; kk++) {
            float4 a4 = *reinterpret_cast<const float4*>(&As[kk*68 + (ty << 2)]);
            float4 b4 = *reinterpret_cast<const float4*>(&Bs[kk*68 + (tx << 2)]);
            float av[4] = {a4.x, a4.y, a4.z, a4.w};
            float bv[4] = {b4.x, b4.y, b4.z, b4.w};
            #pragma unroll
            for (int u = 0; u < 4; u++)
                #pragma unroll
                for (int v = 0; v < 4; v++) acc[u][v] += av[u] * bv[v];
        }
        __syncthreads();
    }
    #pragma unroll
    for (int u = 0; u < 4; u++) {
        int gi = row0 + (ty << 2) + u;
        #pragma unroll
        for (int v = 0; v < 4; v++) {
            int gj = col0 + (tx << 2) + v;
            if (gi < NEQX && gj < NEQX && gj <= gi)
                Sout[gi*LDSM + gj] = acc[u][v];
        }
    }
}

// ---------------- blocked left-looking Cholesky (one CTA per batch) -------
// Lower factor + mirrored upper (mirror gives coalesced row reads later).
__global__ void __launch_bounds__(320) k_chol(int init) {
    float* S = init ? g_S0 : (g_Smat + blockIdx.x*SSTR);
    __shared__ float sp[300*33];   // panel: up to 300 rows x 32 (+1 pad)
    __shared__ float stp[32*32];
    __shared__ float sinvd[32];
    int tid = threadIdx.x;

    for (int p = 0; p < NPAN; p++) {
        int col0 = p * 32;
        int pw = NEQX - col0; if (pw > 32) pw = 32;
        int nrows = NEQX - col0;
        // load panel (rows [col0,300), cols [col0,col0+pw))
        for (int idx = tid; idx < nrows * 32; idx += 320) {
            int r = idx >> 5, c = idx & 31;
            sp[r*33 + c] = (c < pw) ? S[(col0 + r)*LDSM + col0 + c] : 0.f;
        }
        __syncthreads();

        int r = tid;
        bool act = (r < nrows);
        int grow = col0 + r;

        // ---- left-looking update with 8-deep register prefetch ----
        if (col0 > 0) {
            float accu[32];
            #pragma unroll
            for (int c = 0; c < 32; c++) accu[c] = 0.f;
            for (int k0 = 0; k0 < col0; k0 += 32) {
                for (int idx = tid; idx < 1024; idx += 320) {
                    int kk = idx >> 5, c = idx & 31;
                    int gc = col0 + c;
                    stp[idx] = (gc < NEQX) ? S[(k0 + kk)*LDSM + gc] : 0.f;
                }
                __syncthreads();
                if (act) {
                    #pragma unroll
                    for (int kk0 = 0; kk0 < 32; kk0 += 8) {
                        float mv[8];
                        #pragma unroll
                        for (int i = 0; i < 8; i++)
                            mv[i] = S[(k0 + kk0 + i)*LDSM + grow]; // mirror, coalesced, MLP=8
                        #pragma unroll
                        for (int i = 0; i < 8; i++) {
                            #pragma unroll
                            for (int c = 0; c < 32; c++)
                                accu[c] += mv[i] * stp[(kk0 + i)*32 + c];
                        }
                    }
                }
                __syncthreads();
            }
            if (act) {
                #pragma unroll
                for (int c = 0; c < 32; c++) sp[r*33 + c] -= accu[c];
            }
            __syncthreads();
        }

        // ---- register-resident 32x32 diag factorization (warp 0) ----
        if (tid < 32) {
            int lane = tid;
            float row[32];
            #pragma unroll
            for (int j = 0; j < 32; j++) row[j] = sp[lane*33 + j];
            #pragma unroll
            for (int c = 0; c < 32; c++) {
                if (c < pw) {
                    float piv = __shfl_sync(0xffffffffu, row[c], c);
                    float inv = rsqrtf(piv);
                    float d   = piv * inv;
                    float lrc;
                    if (lane == c)      lrc = d;
                    else if (lane > c)  lrc = row[c] * inv;
                    else                lrc = 0.f;
                    row[c] = lrc;
                    if (lane == c) sinvd[c] = inv;
                    #pragma unroll
                    for (int j = 0; j < 32; j++) {
                        if (j > c) {
                            float ljc = __shfl_sync(0xffffffffu, lrc, j);
                            row[j] -= lrc * ljc;   // junk above diag: harmless, never read
                        }
                    }
                }
            }
            #pragma unroll
            for (int j = 0; j < 32; j++) sp[lane*33 + j] = row[j];
        }
        __syncthreads();

        // ---- sub-diagonal rows: per-thread serial triangular solve ----
        if (act && r >= pw) {
            float lr[32];
            float* rp = &sp[r*33];
            #pragma unroll
            for (int c = 0; c < 32; c++) {
                if (c < pw) {
                    float v = rp[c];
                    #pragma unroll
                    for (int j = 0; j < 32; j++)
                        if (j < c) v -= lr[j] * sp[c*33 + j];
                    v *= sinvd[c];
                    lr[c] = v;
                    rp[c] = v;
                }
            }
        }
        __syncthreads();

        // ---- store panel: lower + mirrored upper ----
        for (int idx = tid; idx < nrows * 32; idx += 320) {
            int r2 = idx >> 5, c = idx & 31;
            if (c < pw && r2 >= c) {
                float v = sp[r2*33 + c];
                S[(col0 + r2)*LDSM + col0 + c] = v;
                S[(col0 + c)*LDSM + col0 + r2] = v;
            }
        }
        __syncthreads();
    }
}

// ---------------- triangular solves L L^T x = rhs (one CTA per batch) -----
// Right-looking block scheme: shfl-pipelined diag sweep + parallel tail.
__global__ void __launch_bounds__(320) k_trsolve(int init) {
    int b = blockIdx.x;
    const float* S   = init ? g_S0 : (g_Smat + b*SSTR);
    const float* rhs = g_RHS + b*NEQX;
    float* out       = init ? (g_NU + b*NEQX) : (g_DNU + b*NEQX);
    __shared__ float sy[NEQX];
    __shared__ float db[32*33];
    __shared__ float sinv[32];
    int tid = threadIdx.x;
    int lane = tid & 31;
    if (tid < NEQX) sy[tid] = rhs[tid];
    __syncthreads();

    // forward: L y = rhs
    for (int p = 0; p < NPAN; p++) {
        int col0 = p * 32;
        int pw = NEQX - col0; if (pw > 32) pw = 32;
        for (int idx = tid; idx < 1024; idx += 320) {
            int i = idx >> 5, j = idx & 31;
            db[i*33 + j] = (col0 + i < NEQX && col0 + j < NEQX)
                           ? S[(col0 + i)*LDSM + col0 + j] : 0.f;
        }
        __syncthreads();
        if (tid < 32 && tid < pw) sinv[tid] = 1.0f / db[tid*33 + tid];
        __syncthreads();
        if (tid < 32) {
            float yv = (lane < pw) ? sy[col0 + lane] : 0.f;
            for (int c = 0; c < pw; c++) {
                float t  = __shfl_sync(0xffffffffu, yv, c);
                float yc = t * sinv[c];
                if (lane == c) yv = yc;
                if (lane > c)  yv -= db[lane*33 + c] * yc;
            }
            if (lane < pw) sy[col0 + lane] = yv;
        }
        __syncthreads();
        int rem = NEQX - col0 - pw;
        if (tid < rem) {
            int i = col0 + pw + tid;
            float s = 0.f;
            #pragma unroll 8
            for (int c = 0; c < 32; c++)
                if (c < pw) s += S[(col0 + c)*LDSM + i] * sy[col0 + c]; // mirror, coalesced
            sy[i] -= s;
        }
        __syncthreads();
    }
    // backward: L^T x = y
    for (int p = NPAN - 1; p >= 0; p--) {
        int col0 = p * 32;
        int pw = NEQX - col0; if (pw > 32) pw = 32;
        for (int idx = tid; idx < 1024; idx += 320) {
            int i = idx >> 5, j = idx & 31;
            db[i*33 + j] = (col0 + i < NEQX && col0 + j < NEQX)
                           ? S[(col0 + i)*LDSM + col0 + j] : 0.f;
        }
        __syncthreads();
        if (tid < 32 && tid < pw) sinv[tid] = 1.0f / db[tid*33 + tid];
        __syncthreads();
        if (tid < 32) {
            float yv = (lane < pw) ? sy[col0 + lane] : 0.f;
            for (int c = pw - 1; c >= 0; c--) {
                float t  = __shfl_sync(0xffffffffu, yv, c);
                float xc = t * sinv[c];
                if (lane == c) yv = xc;
                if (lane < c)  yv -= db[c*33 + lane] * xc;  // L^T[lane][c] = L[c][lane]
            }
            if (lane < pw) sy[col0 + lane] = yv;
        }
        __syncthreads();
        if (tid < col0) {
            float s = 0.f;
            #pragma unroll 8
            for (int c = 0; c < 32; c++)
                if (c < pw) s += S[(col0 + c)*LDSM + tid] * sy[col0 + c]; // lower row, coalesced
            sy[tid] -= s;
        }
        __syncthreads();
    }
    if (tid < NEQX) out[tid] = sy[tid];
}

// ---------------- A * vec helper pattern: 4-row ILP per warp ---------------
// ---------------- init rhs: -A (p*Hinv0) - b ----------------
__global__ void __launch_bounds__(768) k_rhs0(const float* __restrict__ A, const float* __restrict__ bv) {
    int b = blockIdx.x, tid = threadIdx.x;
    __shared__ float su[NXX];
    if (tid < NXX) su[tid] = g_P[b*NXX + tid] * g_Hinv0[tid];
    __syncthreads();
    int w = tid >> 5, lane = tid & 31;
    for (int g = w; g < NEQX/4; g += 24) {
        int j = g * 4;
        const float* A0 = A + (size_t)j*NXX;
        float s0=0.f, s1=0.f, s2=0.f, s3=0.f;
        for (int k = lane; k < NXX; k += 32) {
            float u = su[k];
            s0 += A0[k]         * u;
            s1 += A0[NXX + k]   * u;
            s2 += A0[2*NXX + k] * u;
            s3 += A0[3*NXX + k] * u;
        }
        #pragma unroll
        for (int o = 16; o; o >>= 1) {
            s0 += __shfl_xor_sync(0xffffffffu, s0, o);
            s1 += __shfl_xor_sync(0xffffffffu, s1, o);
            s2 += __shfl_xor_sync(0xffffffffu, s2, o);
            s3 += __shfl_xor_sync(0xffffffffu, s3, o);
        }
        if (lane == 0) {
            g_RHS[b*NEQX + j]     = -s0 - bv[j];
            g_RHS[b*NEQX + j + 1] = -s1 - bv[j+1];
            g_RHS[b*NEQX + j + 2] = -s2 - bv[j+2];
            g_RHS[b*NEQX + j + 3] = -s3 - bv[j+3];
        }
    }
}

// ---------------- init z, s, lam, q ----------------
__global__ void __launch_bounds__(768) k_initz(const float* __restrict__ A, const float* __restrict__ h) {
    int b = blockIdx.x, tid = threadIdx.x;
    __shared__ float snu[NEQX];
    if (tid < NEQX) snu[tid] = g_NU[b*NEQX + tid];
    __syncthreads();
    if (tid < NXX) {
        float q = 0.f;
        #pragma unroll 8
        for (int j = 0; j < NEQX; j++) q += A[j*NXX + tid] * snu[j];
        float z = (-g_P[b*NXX + tid] - q) * g_Hinv0[tid];
        float s = fmaxf(h[tid] + z, 1.0f);    // h - G z with G = -I
        g_Qt[b*NXX + tid] = q;
        g_Z [b*NXX + tid] = z;
        g_Sl[b*NXX + tid] = s;
        g_Lm[b*NXX + tid] = 1.0f;
    }
}

// ---------------- per-iteration residuals + dnu RHS ----------------
__global__ void __launch_bounds__(768) k_res(const float* __restrict__ A,
                                             const float* __restrict__ bv,
                                             const float* __restrict__ h) {
    int b = blockIdx.x, tid = threadIdx.x;
    __shared__ float su[NXX];
    __shared__ float red[32];
    float si = 0.f, li = 0.f, part = 0.f;
    if (tid < NXX) {
        si = g_Sl[b*NXX + tid];
        li = g_Lm[b*NXX + tid];
        part = si * li;
    }
    float mu = blkSum(part, red) * (1.0f / (float)NXX);
    if (tid < NXX) {
        float zi = g_Z[b*NXX + tid];
        float pi = g_P[b*NXX + tid];
        float qi = g_Qt[b*NXX + tid];
        float qd = g_Qd[tid];
        float hi = h[tid];
        float rz = qd*zi + pi - li + qi;            // G^T lam = -lam
        float rp = si - zi - hi;                    // G z + s - h
        float rs = si*li - SIGC*mu;
        float hd = qd + li/si;
        float hinv = 1.0f/hd;
        float r1 = -rz + (li*rp - rs)/si;           // -rz - G^T((lam rp - rs)/s)
        g_HINV[b*NXX + tid] = hinv;
        g_R1 [b*NXX + tid] = r1;
        g_RP [b*NXX + tid] = rp;
        g_RS [b*NXX + tid] = rs;
        su[tid] = r1*hinv + zi;                     // A(w+z)-b = A w + re
    }
    __syncthreads();
    int w = tid >> 5, lane = tid & 31;
    for (int g = w; g < NEQX/4; g += 24) {
        int j = g * 4;
        const float* A0 = A + (size_t)j*NXX;
        float s0=0.f, s1=0.f, s2=0.f, s3=0.f;
        for (int k = lane; k < NXX; k += 32) {
            float u = su[k];
            s0 += A0[k]         * u;
            s1 += A0[NXX + k]   * u;
            s2 += A0[2*NXX + k] * u;
            s3 += A0[3*NXX + k] * u;
        }
        #pragma unroll
        for (int o = 16; o; o >>= 1) {
            s0 += __shfl_xor_sync(0xffffffffu, s0, o);
            s1 += __shfl_xor_sync(0xffffffffu, s1, o);
            s2 += __shfl_xor_sync(0xffffffffu, s2, o);
            s3 += __shfl_xor_sync(0xffffffffu, s3, o);
        }
        if (lane == 0) {
            g_RHS[b*NEQX + j]     = s0 - bv[j];
            g_RHS[b*NEQX + j + 1] = s1 - bv[j+1];
            g_RHS[b*NEQX + j + 2] = s2 - bv[j+2];
            g_RHS[b*NEQX + j + 3] = s3 - bv[j+3];
        }
    }
}

// ---------------- step: dz/ds/dlam, alpha, updates ----------------
__global__ void __launch_bounds__(768) k_step(const float* __restrict__ A) {
    int b = blockIdx.x, tid = threadIdx.x;
    __shared__ float sdnu[NEQX];
    __shared__ float red[32];
    if (tid < NEQX) sdnu[tid] = g_DNU[b*NEQX + tid];
    __syncthreads();
    float cand = BIGV;
    float t = 0.f, dz = 0.f, ds = 0.f, dlam = 0.f, si = 0.f, li = 0.f;
    if (tid < NXX) {
        #pragma unroll 8
        for (int j = 0; j < NEQX; j++) t += A[j*NXX + tid] * sdnu[j];
        float r1   = g_R1 [b*NXX + tid];
        float hinv = g_HINV[b*NXX + tid];
        float rp   = g_RP [b*NXX + tid];
        float rs   = g_RS [b*NXX + tid];
        si = g_Sl[b*NXX + tid];
        li = g_Lm[b*NXX + tid];
        dz = (r1 - t) * hinv;
        ds = dz - rp;                         // -rp - G dz
        dlam = (-rs - li*ds) / si;
        if (ds   < 0.f) cand = fminf(cand, -si/ds);
        if (dlam < 0.f) cand = fminf(cand, -li/dlam);
    }
    float am = blkMin(cand, red);
    float alpha = fminf(1.0f, 0.99f * am);
    if (tid < NXX) {
        g_Z [b*NXX + tid] += alpha * dz;
        g_Sl[b*NXX + tid]  = si + alpha * ds;
        g_Lm[b*NXX + tid]  = li + alpha * dlam;
        g_Qt[b*NXX + tid] += alpha * t;       // q = A^T nu incrementally
    }
    if (tid < NEQX) g_NU[b*NEQX + tid] += alpha * sdnu[tid];
}

// ---------------- output copy ----------------
__global__ void k_out(float* __restrict__ out) {
    int b = blockIdx.x, i = threadIdx.x;
    if (i < NXX) out[b*NXX + i] = g_Z[b*NXX + i];
}

// ---------------- launch ----------------
extern "C" void kernel_launch(void* const* d_in, const int* in_sizes, int n_in,
                              void* d_out, int out_size) {
    const float* puzzles = (const float*)d_in[0];
    const float* Q       = (const float*)d_in[1];
    // d_in[2] is G = -I (exploited analytically)
    const float* h       = (const float*)d_in[3];
    const float* A       = (const float*)d_in[4];
    const float* bvec    = (const float*)d_in[5];
    float* out = (float*)d_out;

    // init
    k_setup  <<<BAT, 768>>>(puzzles, Q);
    k_syrk   <<<dim3(15, 1), 256>>>(A, 1);
    k_chol   <<<1, 320>>>(1);
    k_rhs0   <<<BAT, 768>>>(A, bvec);
    k_trsolve<<<BAT, 320>>>(1);
    k_initz  <<<BAT, 768>>>(A, h);

    // 10 PDIPM iterations
    for (int it = 0; it < 10; it++) {
        k_res    <<<BAT, 768>>>(A, bvec, h);
        k_syrk   <<<dim3(15, BAT), 256>>>(A, 0);
        k_chol   <<<BAT, 320>>>(0);
        k_trsolve<<<BAT, 320>>>(0);
        k_step   <<<BAT, 768>>>(A);
    }
    k_out<<<BAT, 768>>>(out);
}

// round 4
// speedup vs baseline: 2.0407x; 1.1154x over previous
#include <cuda_runtime.h>
#include <cuda_bf16.h>
#include <math.h>

// Problem constants
#define NXX   729
#define NEQX  300
#define BAT   16
#define LDSM  320                 // leading dim of S; 320*4B = 10 x 128B lines (line-aligned rows!)
#define SSTR  (NEQX*LDSM)         // 96000 floats per batch S matrix
#define NPAN  10                  // ceil(300/32) panels
#define NB    10                  // row blocks of 32
#define CLW   4                   // cluster width (CTAs per batch in k_chol)
#define SIGC  0.1f
#define BIGV  1e9f

// ---------------- device scratch (no allocations allowed) ----------------
__device__ float g_P   [BAT*NXX];
__device__ float g_Z   [BAT*NXX];
__device__ float g_Sl  [BAT*NXX];
__device__ float g_Lm  [BAT*NXX];
__device__ float g_Qt  [BAT*NXX];   // q = A^T nu
__device__ float g_HINV[BAT*NXX];
__device__ float g_R1  [BAT*NXX];
__device__ float g_RP  [BAT*NXX];
__device__ float g_RS  [BAT*NXX];
__device__ float g_NU  [BAT*NEQX];
__device__ float g_DNU [BAT*NEQX];
__device__ float g_RHS [BAT*NEQX];
__device__ float g_Smat[BAT*SSTR];
__device__ float g_S0  [SSTR];
__device__ float g_Minv[BAT*NPAN*1024];  // per-panel 32x32 inverse of diag L
__device__ float g_Minv0[NPAN*1024];
__device__ float g_Qd  [NXX];
__device__ float g_Hinv0[NXX];

__device__ __forceinline__ void cluster_sync_() {
    asm volatile("barrier.cluster.arrive.aligned;" ::: "memory");
    asm volatile("barrier.cluster.wait.aligned;" ::: "memory");
}

// ---------------- reductions ----------------
__device__ __forceinline__ float blkSum(float v, float* red) {
    #pragma unroll
    for (int o = 16; o; o >>= 1) v += __shfl_xor_sync(0xffffffffu, v, o);
    int w = threadIdx.x >> 5;
    if ((threadIdx.x & 31) == 0) red[w] = v;
    __syncthreads();
    if (threadIdx.x < 32) {
        int nw = blockDim.x >> 5;
        v = (threadIdx.x < nw) ? red[threadIdx.x] : 0.f;
        #pragma unroll
        for (int o = 16; o; o >>= 1) v += __shfl_xor_sync(0xffffffffu, v, o);
        if (threadIdx.x == 0) red[0] = v;
    }
    __syncthreads();
    return red[0];
}

__device__ __forceinline__ float blkMin(float v, float* red) {
    #pragma unroll
    for (int o = 16; o; o >>= 1) v = fminf(v, __shfl_xor_sync(0xffffffffu, v, o));
    int w = threadIdx.x >> 5;
    if ((threadIdx.x & 31) == 0) red[w] = v;
    __syncthreads();
    if (threadIdx.x < 32) {
        int nw = blockDim.x >> 5;
        v = (threadIdx.x < nw) ? red[threadIdx.x] : BIGV;
        #pragma unroll
        for (int o = 16; o; o >>= 1) v = fminf(v, __shfl_xor_sync(0xffffffffu, v, o));
        if (threadIdx.x == 0) red[0] = v;
    }
    __syncthreads();
    return red[0];
}

// ---------------- setup ----------------
__global__ void k_setup(const float* __restrict__ puz, const float* __restrict__ Q) {
    int b = blockIdx.x, i = threadIdx.x;
    if (i < NXX) {
        g_P[b*NXX + i] = -puz[b*NXX + i];
        if (b == 0) {
            float qd = Q[i*NXX + i];
            g_Qd[i] = qd;
            g_Hinv0[i] = 1.0f / qd;
        }
    }
}

// ---------------- batched SYRK: S = A diag(Hinv) A^T (lower triangle) ------
__global__ void __launch_bounds__(256) k_syrk(const float* __restrict__ A, int init) {
    int t = blockIdx.x, b = blockIdx.y;
    int ti = 0;
    while ((ti + 1) * (ti + 2) / 2 <= t) ti++;
    int tj = t - ti * (ti + 1) / 2;
    const float* hv = init ? g_Hinv0 : (g_HINV + b*NXX);
    float* Sout     = init ? g_S0    : (g_Smat + b*SSTR);

    __shared__ __align__(16) float As[32*68];
    __shared__ __align__(16) float Bs[32*68];

    int tid = threadIdx.x;
    int tx = tid & 15, ty = tid >> 4;
    float acc[4][4];
    #pragma unroll
    for (int u = 0; u < 4; u++)
        #pragma unroll
        for (int v = 0; v < 4; v++) acc[u][v] = 0.f;

    int row0 = ti * 64, col0 = tj * 64;
    int cld = tid & 31, rbase = tid >> 5;

    for (int k0 = 0; k0 < NXX; k0 += 32) {
        int k = k0 + cld;
        bool kok = (k < NXX);
        float hval = kok ? hv[k] : 0.f;
        #pragma unroll
        for (int l = 0; l < 8; l++) {
            int r = rbase + l * 8;
            int gi = row0 + r;
            int gj = col0 + r;
            float av = (kok && gi < NEQX) ? A[gi*NXX + k] : 0.f;
            float bv = (kok && gj < NEQX) ? A[gj*NXX + k] : 0.f;
            As[cld*68 + r] = av * hval;
            Bs[cld*68 + r] = bv;
        }
        __syncthreads();
        #pragma unroll
        for (int kk = 0; kk < 32; kk++) {
            float4 a4 = *reinterpret_cast<const float4*>(&As[kk*68 + (ty << 2)]);
            float4 b4 = *reinterpret_cast<const float4*>(&Bs[kk*68 + (tx << 2)]);
            float av[4] = {a4.x, a4.y, a4.z, a4.w};
            float bv[4] = {b4.x, b4.y, b4.z, b4.w};
            #pragma unroll
            for (int u = 0; u < 4; u++)
                #pragma unroll
                for (int v = 0; v < 4; v++) acc[u][v] += av[u] * bv[v];
        }
        __syncthreads();
    }
    #pragma unroll
    for (int u = 0; u < 4; u++) {
        int gi = row0 + (ty << 2) + u;
        #pragma unroll
        for (int v = 0; v < 4; v++) {
            int gj = col0 + (tx << 2) + v;
            if (gi < NEQX && gj < NEQX && gj <= gi)
                Sout[gi*LDSM + gj] = acc[u][v];
        }
    }
}

// ---------------- cluster-parallel right-looking Cholesky ------------------
// grid = nBatch*CLW CTAs, cluster of CLW per batch. Row blocks (32 rows)
// distributed round-robin over cluster ranks. Per panel: owner factors diag,
// sync, all solve own sub-panel rows (+owner warp7 computes Minv), sync,
// tile-GEMM trailing update of own rows. Mirror (upper) copies of the panel
// written for coalesced later reads.
__global__ void __launch_bounds__(256) __cluster_dims__(CLW, 1, 1)
k_chol(int init) {
    int batch = blockIdx.x / CLW;
    unsigned crank;
    asm("mov.u32 %0, %%cluster_ctarank;" : "=r"(crank));
    float* S    = init ? g_S0    : (g_Smat + batch*SSTR);
    float* Minv = init ? g_Minv0 : (g_Minv + batch*(NPAN*1024));
    int tid = threadIdx.x;
    int lane = tid & 31;
    int wid = tid >> 5;

    __shared__ float ld[32*33];
    __shared__ float sinvd[32];
    __shared__ float xi[32*33];
    __shared__ float xj[32*33];

    for (int p = 0; p < NPAN; p++) {
        int col0 = p * 32;
        int pw = NEQX - col0; if (pw > 32) pw = 32;
        int owner = p % CLW;

        // ---- step1: owner warp0 factors diag block ----
        if ((int)crank == owner && wid == 0) {
            float row[32];
            #pragma unroll
            for (int j = 0; j < 32; j++)
                row[j] = (lane < pw && j < pw) ? S[(col0+lane)*LDSM + col0 + j] : 0.f;
            #pragma unroll
            for (int c = 0; c < 32; c++) {
                if (c < pw) {
                    float piv = __shfl_sync(0xffffffffu, row[c], c);
                    float inv = rsqrtf(piv);
                    float d   = piv * inv;
                    float lrc;
                    if (lane == c)      lrc = d;
                    else if (lane > c)  lrc = row[c] * inv;
                    else                lrc = 0.f;
                    row[c] = lrc;
                    #pragma unroll
                    for (int j = 0; j < 32; j++) {
                        if (j > c) {
                            float ljc = __shfl_sync(0xffffffffu, lrc, j);
                            row[j] -= lrc * ljc;
                        }
                    }
                }
            }
            if (lane < pw) {
                #pragma unroll
                for (int j = 0; j < 32; j++)
                    S[(col0+lane)*LDSM + col0 + j] = row[j];
            }
        }
        cluster_sync_();

        // ---- all CTAs: load L diag into smem ----
        for (int idx = tid; idx < 1024; idx += 256) {
            int i = idx >> 5, j = idx & 31;
            ld[i*33 + j] = (i < pw) ? S[(col0+i)*LDSM + col0 + j] : 0.f;
        }
        __syncthreads();
        if (tid < 32) sinvd[tid] = (tid < pw && ld[tid*33+tid] != 0.f) ? (1.0f / ld[tid*33+tid]) : 0.f;
        __syncthreads();

        // ---- step2: panel solve for own blocks > p (threads 0..95) ----
        {
            int slot = 0;
            for (int bi = crank; bi < NB; bi += CLW) {
                if (bi <= p) { continue; }
                int r0 = bi * 32;
                int nr = NEQX - r0; if (nr > 32) nr = 32;
                int r = tid - slot * 32;
                if (r >= 0 && r < nr) {
                    int gr = r0 + r;
                    float lr[32];
                    float* Srow = S + (size_t)gr*LDSM + col0;
                    #pragma unroll
                    for (int c = 0; c < 32; c++) {
                        if (c < pw) {
                            float v = Srow[c];
                            #pragma unroll
                            for (int j = 0; j < 32; j++)
                                if (j < c) v -= lr[j] * ld[c*33 + j];
                            v *= sinvd[c];
                            lr[c] = v;
                        } else lr[c] = 0.f;
                    }
                    #pragma unroll
                    for (int c = 0; c < 32; c++) {
                        if (c < pw) {
                            Srow[c] = lr[c];
                            S[(col0+c)*LDSM + gr] = lr[c];   // mirror
                        }
                    }
                }
                slot++;
            }
        }
        // ---- owner warp7 (tid 224..255, never used by step2): Minv ----
        if ((int)crank == owner && wid == 7) {
            int c = lane;
            float xc[32];
            #pragma unroll
            for (int j = 0; j < 32; j++) xc[j] = 0.f;
            if (c < pw) xc[c] = sinvd[c];
            #pragma unroll
            for (int rr = 1; rr < 32; rr++) {
                float s = 0.f;
                #pragma unroll
                for (int j = 0; j < 32; j++)
                    if (j < rr) s += ld[rr*33 + j] * xc[j];
                if (rr > c && rr < pw && c < pw) xc[rr] = -s * sinvd[rr];
            }
            float* Mp = Minv + p * 1024;
            #pragma unroll
            for (int rr = 0; rr < 32; rr++) Mp[rr*32 + c] = xc[rr];
        }
        cluster_sync_();

        // ---- step3: trailing update of own row blocks ----
        for (int bi = crank; bi < NB; bi += CLW) {
            if (bi <= p) continue;
            int nri = NEQX - bi*32; if (nri > 32) nri = 32;
            for (int idx = tid; idx < 1024; idx += 256) {
                int k = idx >> 5, r = idx & 31;
                xi[r*33 + k] = (r < nri && k < pw) ? S[(col0+k)*LDSM + bi*32 + r] : 0.f;
            }
            __syncthreads();
            for (int jb = p + 1; jb <= bi; jb++) {
                int nrj = NEQX - jb*32; if (nrj > 32) nrj = 32;
                const float* xjp;
                if (jb == bi) {
                    xjp = xi;
                } else {
                    for (int idx = tid; idx < 1024; idx += 256) {
                        int k = idx >> 5, r = idx & 31;
                        xj[r*33 + k] = (r < nrj && k < pw) ? S[(col0+k)*LDSM + jb*32 + r] : 0.f;
                    }
                    xjp = xj;
                }
                __syncthreads();
                int r  = tid >> 3;
                int c0 = (tid & 7) << 2;
                float a0 = 0.f, a1 = 0.f, a2 = 0.f, a3 = 0.f;
                #pragma unroll
                for (int k = 0; k < 32; k++) {
                    float xv = xi[r*33 + k];
                    a0 += xv * xjp[(c0+0)*33 + k];
                    a1 += xv * xjp[(c0+1)*33 + k];
                    a2 += xv * xjp[(c0+2)*33 + k];
                    a3 += xv * xjp[(c0+3)*33 + k];
                }
                int gr = bi*32 + r;
                if (gr < NEQX && r < nri) {
                    float* Sr = S + (size_t)gr*LDSM + jb*32;
                    if (c0 + 0 < nrj) Sr[c0+0] -= a0;
                    if (c0 + 1 < nrj) Sr[c0+1] -= a1;
                    if (c0 + 2 < nrj) Sr[c0+2] -= a2;
                    if (c0 + 3 < nrj) Sr[c0+3] -= a3;
                }
                __syncthreads();
            }
        }
        // no cluster sync needed here: next panel's cross-CTA reads are all
        // covered by the two syncs above (ownership argument).
    }
}

// ---------------- triangular solves using stored panel inverses -----------
__global__ void __launch_bounds__(320) k_trsolve(int init) {
    int b = blockIdx.x;
    const float* S    = init ? g_S0    : (g_Smat + b*SSTR);
    const float* Minv = init ? g_Minv0 : (g_Minv + b*(NPAN*1024));
    const float* rhs  = g_RHS + b*NEQX;
    float* out        = init ? (g_NU + b*NEQX) : (g_DNU + b*NEQX);
    __shared__ float sy[320];
    __shared__ float mv[32*33];
    int tid = threadIdx.x;
    int lane = tid & 31;
    sy[tid] = (tid < NEQX) ? rhs[tid] : 0.f;
    __syncthreads();

    // forward: L y = rhs
    for (int p = 0; p < NPAN; p++) {
        int col0 = p * 32;
        int pw = NEQX - col0; if (pw > 32) pw = 32;
        const float* Mp = Minv + p * 1024;
        for (int idx = tid; idx < 1024; idx += 320) {
            int i = idx >> 5, j = idx & 31;
            mv[i*33 + j] = Mp[i*32 + j];
        }
        __syncthreads();
        if (tid < 32) {
            float y = 0.f;
            #pragma unroll 8
            for (int j = 0; j < 32; j++) y += mv[lane*33 + j] * sy[col0 + j];
            __syncwarp();
            if (lane < pw) sy[col0 + lane] = y;
        }
        __syncthreads();
        int rem = NEQX - col0 - pw;
        if (tid < rem) {
            int i = col0 + pw + tid;
            float s = 0.f;
            #pragma unroll 8
            for (int c = 0; c < 32; c++)
                if (c < pw) s += S[(col0 + c)*LDSM + i] * sy[col0 + c]; // mirror, coalesced
            sy[i] -= s;
        }
        __syncthreads();
    }
    // backward: L^T x = y  →  x_p = Minv_p^T y_p
    for (int p = NPAN - 1; p >= 0; p--) {
        int col0 = p * 32;
        int pw = NEQX - col0; if (pw > 32) pw = 32;
        const float* Mp = Minv + p * 1024;
        for (int idx = tid; idx < 1024; idx += 320) {
            int i = idx >> 5, j = idx & 31;
            mv[i*33 + j] = Mp[i*32 + j];
        }
        __syncthreads();
        if (tid < 32) {
            float x = 0.f;
            #pragma unroll 8
            for (int j = 0; j < 32; j++) x += mv[j*33 + lane] * sy[col0 + j];
            __syncwarp();
            if (lane < pw) sy[col0 + lane] = x;
        }
        __syncthreads();
        if (tid < col0) {
            float s = 0.f;
            #pragma unroll 8
            for (int c = 0; c < 32; c++)
                if (c < pw) s += S[(col0 + c)*LDSM + tid] * sy[col0 + c]; // lower row, coalesced
            sy[tid] -= s;
        }
        __syncthreads();
    }
    if (tid < NEQX) out[tid] = sy[tid];
}

// ---------------- init rhs: -A (p*Hinv0) - b ----------------
__global__ void __launch_bounds__(768) k_rhs0(const float* __restrict__ A, const float* __restrict__ bv) {
    int b = blockIdx.x, tid = threadIdx.x;
    __shared__ float su[NXX];
    if (tid < NXX) su[tid] = g_P[b*NXX + tid] * g_Hinv0[tid];
    __syncthreads();
    int w = tid >> 5, lane = tid & 31;
    for (int g = w; g < NEQX/4; g += 24) {
        int j = g * 4;
        const float* A0 = A + (size_t)j*NXX;
        float s0=0.f, s1=0.f, s2=0.f, s3=0.f;
        for (int k = lane; k < NXX; k += 32) {
            float u = su[k];
            s0 += A0[k]         * u;
            s1 += A0[NXX + k]   * u;
            s2 += A0[2*NXX + k] * u;
            s3 += A0[3*NXX + k] * u;
        }
        #pragma unroll
        for (int o = 16; o; o >>= 1) {
            s0 += __shfl_xor_sync(0xffffffffu, s0, o);
            s1 += __shfl_xor_sync(0xffffffffu, s1, o);
            s2 += __shfl_xor_sync(0xffffffffu, s2, o);
            s3 += __shfl_xor_sync(0xffffffffu, s3, o);
        }
        if (lane == 0) {
            g_RHS[b*NEQX + j]     = -s0 - bv[j];
            g_RHS[b*NEQX + j + 1] = -s1 - bv[j+1];
            g_RHS[b*NEQX + j + 2] = -s2 - bv[j+2];
            g_RHS[b*NEQX + j + 3] = -s3 - bv[j+3];
        }
    }
}

// ---------------- init z, s, lam, q ----------------
__global__ void __launch_bounds__(768) k_initz(const float* __restrict__ A, const float* __restrict__ h) {
    int b = blockIdx.x, tid = threadIdx.x;
    __shared__ float snu[NEQX];
    if (tid < NEQX) snu[tid] = g_NU[b*NEQX + tid];
    __syncthreads();
    if (tid < NXX) {
        float q = 0.f;
        #pragma unroll 8
        for (int j = 0; j < NEQX; j++) q += A[j*NXX + tid] * snu[j];
        float z = (-g_P[b*NXX + tid] - q) * g_Hinv0[tid];
        float s = fmaxf(h[tid] + z, 1.0f);    // h - G z with G = -I
        g_Qt[b*NXX + tid] = q;
        g_Z [b*NXX + tid] = z;
        g_Sl[b*NXX + tid] = s;
        g_Lm[b*NXX + tid] = 1.0f;
    }
}

// ---------------- per-iteration residuals + dnu RHS ----------------
__global__ void __launch_bounds__(768) k_res(const float* __restrict__ A,
                                             const float* __restrict__ bv,
                                             const float* __restrict__ h) {
    int b = blockIdx.x, tid = threadIdx.x;
    __shared__ float su[NXX];
    __shared__ float red[32];
    float si = 0.f, li = 0.f, part = 0.f;
    if (tid < NXX) {
        si = g_Sl[b*NXX + tid];
        li = g_Lm[b*NXX + tid];
        part = si * li;
    }
    float mu = blkSum(part, red) * (1.0f / (float)NXX);
    if (tid < NXX) {
        float zi = g_Z[b*NXX + tid];
        float pi = g_P[b*NXX + tid];
        float qi = g_Qt[b*NXX + tid];
        float qd = g_Qd[tid];
        float hi = h[tid];
        float rz = qd*zi + pi - li + qi;            // G^T lam = -lam
        float rp = si - zi - hi;                    // G z + s - h
        float rs = si*li - SIGC*mu;
        float hd = qd + li/si;
        float hinv = 1.0f/hd;
        float r1 = -rz + (li*rp - rs)/si;
        g_HINV[b*NXX + tid] = hinv;
        g_R1 [b*NXX + tid] = r1;
        g_RP [b*NXX + tid] = rp;
        g_RS [b*NXX + tid] = rs;
        su[tid] = r1*hinv + zi;                     // A(w+z)-b = A w + re
    }
    __syncthreads();
    int w = tid >> 5, lane = tid & 31;
    for (int g = w; g < NEQX/4; g += 24) {
        int j = g * 4;
        const float* A0 = A + (size_t)j*NXX;
        float s0=0.f, s1=0.f, s2=0.f, s3=0.f;
        for (int k = lane; k < NXX; k += 32) {
            float u = su[k];
            s0 += A0[k]         * u;
            s1 += A0[NXX + k]   * u;
            s2 += A0[2*NXX + k] * u;
            s3 += A0[3*NXX + k] * u;
        }
        #pragma unroll
        for (int o = 16; o; o >>= 1) {
            s0 += __shfl_xor_sync(0xffffffffu, s0, o);
            s1 += __shfl_xor_sync(0xffffffffu, s1, o);
            s2 += __shfl_xor_sync(0xffffffffu, s2, o);
            s3 += __shfl_xor_sync(0xffffffffu, s3, o);
        }
        if (lane == 0) {
            g_RHS[b*NEQX + j]     = s0 - bv[j];
            g_RHS[b*NEQX + j + 1] = s1 - bv[j+1];
            g_RHS[b*NEQX + j + 2] = s2 - bv[j+2];
            g_RHS[b*NEQX + j + 3] = s3 - bv[j+3];
        }
    }
}

// ---------------- step: dz/ds/dlam, alpha, updates ----------------
__global__ void __launch_bounds__(768) k_step(const float* __restrict__ A) {
    int b = blockIdx.x, tid = threadIdx.x;
    __shared__ float sdnu[NEQX];
    __shared__ float red[32];
    if (tid < NEQX) sdnu[tid] = g_DNU[b*NEQX + tid];
    __syncthreads();
    float cand = BIGV;
    float t = 0.f, dz = 0.f, ds = 0.f, dlam = 0.f, si = 0.f, li = 0.f;
    if (tid < NXX) {
        #pragma unroll 8
        for (int j = 0; j < NEQX; j++) t += A[j*NXX + tid] * sdnu[j];
        float r1   = g_R1 [b*NXX + tid];
        float hinv = g_HINV[b*NXX + tid];
        float rp   = g_RP [b*NXX + tid];
        float rs   = g_RS [b*NXX + tid];
        si = g_Sl[b*NXX + tid];
        li = g_Lm[b*NXX + tid];
        dz = (r1 - t) * hinv;
        ds = dz - rp;                         // -rp - G dz
        dlam = (-rs - li*ds) / si;
        if (ds   < 0.f) cand = fminf(cand, -si/ds);
        if (dlam < 0.f) cand = fminf(cand, -li/dlam);
    }
    float am = blkMin(cand, red);
    float alpha = fminf(1.0f, 0.99f * am);
    if (tid < NXX) {
        g_Z [b*NXX + tid] += alpha * dz;
        g_Sl[b*NXX + tid]  = si + alpha * ds;
        g_Lm[b*NXX + tid]  = li + alpha * dlam;
        g_Qt[b*NXX + tid] += alpha * t;       // q = A^T nu incrementally
    }
    if (tid < NEQX) g_NU[b*NEQX + tid] += alpha * sdnu[tid];
}

// ---------------- output copy ----------------
__global__ void k_out(float* __restrict__ out) {
    int b = blockIdx.x, i = threadIdx.x;
    if (i < NXX) out[b*NXX + i] = g_Z[b*NXX + i];
}

// ---------------- launch ----------------
extern "C" void kernel_launch(void* const* d_in, const int* in_sizes, int n_in,
                              void* d_out, int out_size) {
    const float* puzzles = (const float*)d_in[0];
    const float* Q       = (const float*)d_in[1];
    // d_in[2] is G = -I (exploited analytically)
    const float* h       = (const float*)d_in[3];
    const float* A       = (const float*)d_in[4];
    const float* bvec    = (const float*)d_in[5];
    float* out = (float*)d_out;

    // init
    k_setup  <<<BAT, 768>>>(puzzles, Q);
    k_syrk   <<<dim3(15, 1), 256>>>(A, 1);
    k_chol   <<<CLW, 256>>>(1);
    k_rhs0   <<<BAT, 768>>>(A, bvec);
    k_trsolve<<<BAT, 320>>>(1);
    k_initz  <<<BAT, 768>>>(A, h);

    // 10 PDIPM iterations
    for (int it = 0; it < 10; it++) {
        k_res    <<<BAT, 768>>>(A, bvec, h);
        k_syrk   <<<dim3(15, BAT), 256>>>(A, 0);
        k_chol   <<<BAT*CLW, 256>>>(0);
        k_trsolve<<<BAT, 320>>>(0);
        k_step   <<<BAT, 768>>>(A);
    }
    k_out<<<BAT, 768>>>(out);
}

// round 7
// speedup vs baseline: 2.0711x; 1.0149x over previous
#include <cuda_runtime.h>
#include <cuda_bf16.h>
#include <math.h>

// Problem constants
#define NXX   729
#define NEQX  300
#define BAT   16
#define LDSM  320                 // rows line-aligned: 320*4B = 10 x 128B lines
#define SSTR  (NEQX*LDSM)
#define NPAN  10
#define NB    10
#define CLW   5                   // 10 blocks / 5 CTAs = exactly 2 each
#define SIGC  0.1f
#define BIGV  1e9f

// ---------------- device scratch ----------------
__device__ float g_P   [BAT*NXX];
__device__ float g_Z   [BAT*NXX];
__device__ float g_Sl  [BAT*NXX];
__device__ float g_Lm  [BAT*NXX];
__device__ float g_Qt  [BAT*NXX];
__device__ float g_HINV[BAT*NXX];
__device__ float g_R1  [BAT*NXX];
__device__ float g_RP  [BAT*NXX];
__device__ float g_RS  [BAT*NXX];
__device__ float g_NU  [BAT*NEQX];
__device__ float g_RHS [BAT*NEQX];
__device__ float g_Smat[BAT*SSTR];
__device__ float g_S0  [SSTR];
__device__ float g_Minv[BAT*NPAN*1024];
__device__ float g_Minv0[NPAN*1024];
__device__ float g_Qd  [NXX];
__device__ float g_Hinv0[NXX];

__device__ __forceinline__ void cluster_sync_() {
    asm volatile("barrier.cluster.arrive.aligned;" ::: "memory");
    asm volatile("barrier.cluster.wait.aligned;" ::: "memory");
}

// ---------------- reductions ----------------
__device__ __forceinline__ float blkSum(float v, float* red) {
    #pragma unroll
    for (int o = 16; o; o >>= 1) v += __shfl_xor_sync(0xffffffffu, v, o);
    int w = threadIdx.x >> 5;
    if ((threadIdx.x & 31) == 0) red[w] = v;
    __syncthreads();
    if (threadIdx.x < 32) {
        int nw = blockDim.x >> 5;
        v = (threadIdx.x < nw) ? red[threadIdx.x] : 0.f;
        #pragma unroll
        for (int o = 16; o; o >>= 1) v += __shfl_xor_sync(0xffffffffu, v, o);
        if (threadIdx.x == 0) red[0] = v;
    }
    __syncthreads();
    return red[0];
}

__device__ __forceinline__ float blkMin(float v, float* red) {
    #pragma unroll
    for (int o = 16; o; o >>= 1) v = fminf(v, __shfl_xor_sync(0xffffffffu, v, o));
    int w = threadIdx.x >> 5;
    if ((threadIdx.x & 31) == 0) red[w] = v;
    __syncthreads();
    if (threadIdx.x < 32) {
        int nw = blockDim.x >> 5;
        v = (threadIdx.x < nw) ? red[threadIdx.x] : BIGV;
        #pragma unroll
        for (int o = 16; o; o >>= 1) v = fminf(v, __shfl_xor_sync(0xffffffffu, v, o));
        if (threadIdx.x == 0) red[0] = v;
    }
    __syncthreads();
    return red[0];
}

// ---------------- setup ----------------
__global__ void k_setup(const float* __restrict__ puz, const float* __restrict__ Q) {
    int b = blockIdx.x, i = threadIdx.x;
    if (i < NXX) {
        g_P[b*NXX + i] = -puz[b*NXX + i];
        if (b == 0) {
            float qd = Q[i*NXX + i];
            g_Qd[i] = qd;
            g_Hinv0[i] = 1.0f / qd;
        }
    }
}

// ---------------- batched SYRK: S = A diag(Hinv) A^T (lower triangle) ------
__global__ void __launch_bounds__(256) k_syrk(const float* __restrict__ A, int init) {
    int t = blockIdx.x, b = blockIdx.y;
    int ti = 0;
    while ((ti + 1) * (ti + 2) / 2 <= t) ti++;
    int tj = t - ti * (ti + 1) / 2;
    const float* hv = init ? g_Hinv0 : (g_HINV + b*NXX);
    float* Sout     = init ? g_S0    : (g_Smat + b*SSTR);

    __shared__ __align__(16) float As[32*68];
    __shared__ __align__(16) float Bs[32*68];

    int tid = threadIdx.x;
    int tx = tid & 15, ty = tid >> 4;
    float acc[4][4];
    #pragma unroll
    for (int u = 0; u < 4; u++)
        #pragma unroll
        for (int v = 0; v < 4; v++) acc[u][v] = 0.f;

    int row0 = ti * 64, col0 = tj * 64;
    int cld = tid & 31, rbase = tid >> 5;

    for (int k0 = 0; k0 < NXX; k0 += 32) {
        int k = k0 + cld;
        bool kok = (k < NXX);
        float hval = kok ? hv[k] : 0.f;
        #pragma unroll
        for (int l = 0; l < 8; l++) {
            int r = rbase + l * 8;
            int gi = row0 + r;
            int gj = col0 + r;
            float av = (kok && gi < NEQX) ? A[gi*NXX + k] : 0.f;
            float bv = (kok && gj < NEQX) ? A[gj*NXX + k] : 0.f;
            As[cld*68 + r] = av * hval;
            Bs[cld*68 + r] = bv;
        }
        __syncthreads();
        #pragma unroll
        for (int kk = 0; kk < 32; kk++) {
            float4 a4 = *reinterpret_cast<const float4*>(&As[kk*68 + (ty << 2)]);
            float4 b4 = *reinterpret_cast<const float4*>(&Bs[kk*68 + (tx << 2)]);
            float av[4] = {a4.x, a4.y, a4.z, a4.w};
            float bv[4] = {b4.x, b4.y, b4.z, b4.w};
            #pragma unroll
            for (int u = 0; u < 4; u++)
                #pragma unroll
                for (int v = 0; v < 4; v++) acc[u][v] += av[u] * bv[v];
        }
        __syncthreads();
    }
    #pragma unroll
    for (int u = 0; u < 4; u++) {
        int gi = row0 + (ty << 2) + u;
        #pragma unroll
        for (int v = 0; v < 4; v++) {
            int gj = col0 + (tx << 2) + v;
            if (gi < NEQX && gj < NEQX && gj <= gi)
                Sout[gi*LDSM + gj] = acc[u][v];
        }
    }
}

// ---------------- cluster-parallel right-looking Cholesky ------------------
// CLW=5 CTAs per batch, 2 row-blocks each (bi = crank, crank+5).
// Per panel: all CTAs redundantly factor the 32x32 diag in registers and
// build Minv; panel solve is a parallel GEMM X = B * Minv^T; trailing update
// is tiled GEMMs over own rows. Two cluster syncs per panel.
__global__ void __launch_bounds__(256) __cluster_dims__(CLW, 1, 1)
k_chol(int init) {
    int batch = blockIdx.x / CLW;
    unsigned crank;
    asm("mov.u32 %0, %%cluster_ctarank;" : "=r"(crank));
    float* S    = init ? g_S0    : (g_Smat + batch*SSTR);
    float* Minv = init ? g_Minv0 : (g_Minv + batch*(NPAN*1024));
    int tid = threadIdx.x;
    int lane = tid & 31;
    int wid = tid >> 5;

    __shared__ float ld[32*33];
    __shared__ float mi[32*33];
    __shared__ float sinvd[32];
    __shared__ float pan[64*33];   // own 2 blocks: staged B, then X
    __shared__ float xj[32*33];

    for (int p = 0; p < NPAN; p++) {
        int col0 = p * 32;
        int pw = NEQX - col0; if (pw > 32) pw = 32;
        int owner = p % CLW;

        cluster_sync_();   // prior trailing updates visible everywhere

        // ---- phase A: warp0 factors diag (redundant on all CTAs);
        //      warps 1..7 stage own sub-panel rows (coalesced)
        if (wid == 0) {
            float row[32];
            #pragma unroll
            for (int j = 0; j < 32; j++)
                row[j] = (lane < pw && j < pw) ? S[(col0+lane)*LDSM + col0 + j] : 0.f;
            float sinv = 0.f;
            #pragma unroll
            for (int c = 0; c < 32; c++) {
                if (c < pw) {
                    float piv = __shfl_sync(0xffffffffu, row[c], c);
                    float inv = rsqrtf(piv);
                    float d   = piv * inv;
                    float lrc;
                    if (lane == c)      lrc = d;
                    else if (lane > c)  lrc = row[c] * inv;
                    else                lrc = 0.f;
                    row[c] = lrc;
                    if (lane == c) sinv = 1.0f / d;
                    #pragma unroll
                    for (int j = 0; j < 32; j++) {
                        if (j > c) {
                            float ljc = __shfl_sync(0xffffffffu, lrc, j);
                            row[j] -= lrc * ljc;
                        }
                    }
                }
            }
            sinvd[lane] = sinv;
            #pragma unroll
            for (int j = 0; j < 32; j++) ld[lane*33 + j] = row[j];
            if ((int)crank == owner && lane < pw) {
                #pragma unroll
                for (int j = 0; j < 32; j++)
                    S[(col0+lane)*LDSM + col0 + j] = row[j];
            }
        } else {
            #pragma unroll
            for (int s = 0; s < 2; s++) {
                int bi = (int)crank + s*CLW;
                if (bi <= p) continue;
                int nr = NEQX - bi*32; if (nr > 32) nr = 32;
                for (int idx = tid - 32; idx < 1024; idx += 224) {
                    int r = idx >> 5, c = idx & 31;
                    pan[(s*32+r)*33 + c] = (r < nr && c < pw)
                        ? S[(bi*32+r)*LDSM + col0 + c] : 0.f;
                }
            }
        }
        __syncthreads();

        // ---- phase B: warp0 computes Minv = inv(L_d) into mi ----
        if (wid == 0) {
            int c = lane;
            float xc[32];
            #pragma unroll
            for (int j = 0; j < 32; j++) xc[j] = 0.f;
            if (c < pw) xc[c] = sinvd[c];
            #pragma unroll
            for (int rr = 1; rr < 32; rr++) {
                float s = 0.f;
                #pragma unroll
                for (int j = 0; j < 32; j++)
                    if (j < rr) s += ld[rr*33 + j] * xc[j];
                if (rr > c && rr < pw && c < pw) xc[rr] = -s * sinvd[rr];
            }
            #pragma unroll
            for (int rr = 0; rr < 32; rr++) mi[rr*33 + c] = xc[rr];
            if ((int)crank == owner) {
                float* Mp = Minv + p * 1024;
                #pragma unroll
                for (int rr = 0; rr < 32; rr++) Mp[rr*32 + c] = xc[rr];
            }
        }
        __syncthreads();

        // ---- phase C: panel solve as GEMM  X = B * Minv^T ----
        #pragma unroll
        for (int s = 0; s < 2; s++) {
            int bi = (int)crank + s*CLW;
            if (bi <= p) continue;
            int r  = tid >> 3;
            int c0 = (tid & 7) << 2;
            float breg[32];
            #pragma unroll
            for (int j = 0; j < 32; j++) breg[j] = pan[(s*32+r)*33 + j];
            float a0=0.f, a1=0.f, a2=0.f, a3=0.f;
            #pragma unroll
            for (int j = 0; j < 32; j++) {
                float bj = breg[j];
                a0 += bj * mi[(c0+0)*33 + j];
                a1 += bj * mi[(c0+1)*33 + j];
                a2 += bj * mi[(c0+2)*33 + j];
                a3 += bj * mi[(c0+3)*33 + j];
            }
            __syncwarp();
            pan[(s*32+r)*33 + c0 + 0] = a0;
            pan[(s*32+r)*33 + c0 + 1] = a1;
            pan[(s*32+r)*33 + c0 + 2] = a2;
            pan[(s*32+r)*33 + c0 + 3] = a3;
        }
        __syncthreads();

        // ---- phase D: write X to gmem, lower + mirror (both coalesced) ----
        #pragma unroll
        for (int s = 0; s < 2; s++) {
            int bi = (int)crank + s*CLW;
            if (bi <= p) continue;
            int nr = NEQX - bi*32; if (nr > 32) nr = 32;
            for (int idx = tid; idx < 1024; idx += 256) {
                int r = idx >> 5, c = idx & 31;
                if (r < nr && c < pw)
                    S[(bi*32+r)*LDSM + col0 + c] = pan[(s*32+r)*33 + c];
            }
            for (int idx = tid; idx < 1024; idx += 256) {
                int c = idx >> 5, r = idx & 31;
                if (r < nr && c < pw)
                    S[(col0+c)*LDSM + bi*32 + r] = pan[(s*32+r)*33 + c];
            }
        }
        cluster_sync_();

        // ---- phase E: trailing update of own row blocks ----
        #pragma unroll
        for (int s = 0; s < 2; s++) {
            int bi = (int)crank + s*CLW;
            if (bi <= p) continue;
            int nri = NEQX - bi*32; if (nri > 32) nri = 32;
            for (int jb = p + 1; jb <= bi; jb++) {
                int nrj = NEQX - jb*32; if (nrj > 32) nrj = 32;
                int d = jb - (int)crank;
                int sj = (d >= 0 && d % CLW == 0) ? d / CLW : -1;
                if (sj >= 0 && sj < 2) {
                    for (int idx = tid; idx < 1024; idx += 256) {
                        int k = idx >> 5, c = idx & 31;
                        xj[k*33 + c] = pan[(sj*32+c)*33 + k];
                    }
                } else {
                    for (int idx = tid; idx < 1024; idx += 256) {
                        int k = idx >> 5, c = idx & 31;
                        xj[k*33 + c] = (c < nrj && k < pw)
                            ? S[(col0+k)*LDSM + jb*32 + c] : 0.f;
                    }
                }
                __syncthreads();
                int r  = tid >> 3;
                int c0 = (tid & 7) << 2;
                float a0=0.f, a1=0.f, a2=0.f, a3=0.f;
                #pragma unroll
                for (int k = 0; k < 32; k++) {
                    float xv = pan[(s*32+r)*33 + k];
                    a0 += xv * xj[k*33 + c0 + 0];
                    a1 += xv * xj[k*33 + c0 + 1];
                    a2 += xv * xj[k*33 + c0 + 2];
                    a3 += xv * xj[k*33 + c0 + 3];
                }
                int gr = bi*32 + r;
                if (r < nri) {
                    float* Sr = S + (size_t)gr*LDSM + jb*32;
                    if (c0 + 0 < nrj) Sr[c0+0] -= a0;
                    if (c0 + 1 < nrj) Sr[c0+1] -= a1;
                    if (c0 + 2 < nrj) Sr[c0+2] -= a2;
                    if (c0 + 3 < nrj) Sr[c0+3] -= a3;
                }
                __syncthreads();
            }
        }
    }
}

// ---------------- standalone triangular solve (init only) -----------------
__global__ void __launch_bounds__(320) k_trsolve(int init) {
    int b = blockIdx.x;
    const float* S    = init ? g_S0    : (g_Smat + b*SSTR);
    const float* Minv = init ? g_Minv0 : (g_Minv + b*(NPAN*1024));
    const float* rhs  = g_RHS + b*NEQX;
    float* out        = g_NU + b*NEQX;
    __shared__ float sy[320];
    __shared__ float mv[32*33];
    int tid = threadIdx.x;
    int lane = tid & 31;
    sy[tid] = (tid < NEQX) ? rhs[tid] : 0.f;
    __syncthreads();
    for (int p = 0; p < NPAN; p++) {
        int col0 = p * 32;
        int pw = NEQX - col0; if (pw > 32) pw = 32;
        const float* Mp = Minv + p * 1024;
        for (int idx = tid; idx < 1024; idx += 320) {
            int i = idx >> 5, j = idx & 31;
            mv[i*33 + j] = Mp[i*32 + j];
        }
        __syncthreads();
        if (tid < 32) {
            float y = 0.f;
            #pragma unroll 8
            for (int j = 0; j < 32; j++) y += mv[lane*33 + j] * sy[col0 + j];
            __syncwarp();
            if (lane < pw) sy[col0 + lane] = y;
        }
        __syncthreads();
        int rem = NEQX - col0 - pw;
        if (tid < rem) {
            int i = col0 + pw + tid;
            float s = 0.f;
            #pragma unroll 8
            for (int c = 0; c < 32; c++)
                if (c < pw) s += S[(col0 + c)*LDSM + i] * sy[col0 + c];
            sy[i] -= s;
        }
        __syncthreads();
    }
    for (int p = NPAN - 1; p >= 0; p--) {
        int col0 = p * 32;
        int pw = NEQX - col0; if (pw > 32) pw = 32;
        const float* Mp = Minv + p * 1024;
        for (int idx = tid; idx < 1024; idx += 320) {
            int i = idx >> 5, j = idx & 31;
            mv[i*33 + j] = Mp[i*32 + j];
        }
        __syncthreads();
        if (tid < 32) {
            float x = 0.f;
            #pragma unroll 8
            for (int j = 0; j < 32; j++) x += mv[j*33 + lane] * sy[col0 + j];
            __syncwarp();
            if (lane < pw) sy[col0 + lane] = x;
        }
        __syncthreads();
        if (tid < col0) {
            float s = 0.f;
            #pragma unroll 8
            for (int c = 0; c < 32; c++)
                if (c < pw) s += S[(col0 + c)*LDSM + tid] * sy[col0 + c];
            sy[tid] -= s;
        }
        __syncthreads();
    }
    if (tid < NEQX) out[tid] = sy[tid];
}

// ---------------- fused trsolve + step ----------------
__global__ void __launch_bounds__(768) k_stepsolve(const float* __restrict__ A) {
    int b = blockIdx.x, tid = threadIdx.x, lane = tid & 31;
    const float* S    = g_Smat + b*SSTR;
    const float* Minv = g_Minv + b*(NPAN*1024);
    __shared__ float sy[320];
    __shared__ float mv[32*33];
    __shared__ float red[32];
    if (tid < 320) sy[tid] = (tid < NEQX) ? g_RHS[b*NEQX + tid] : 0.f;
    __syncthreads();

    // forward: L y = rhs
    for (int p = 0; p < NPAN; p++) {
        int col0 = p * 32;
        int pw = NEQX - col0; if (pw > 32) pw = 32;
        const float* Mp = Minv + p * 1024;
        for (int idx = tid; idx < 1024; idx += 768) {
            int i = idx >> 5, j = idx & 31;
            mv[i*33 + j] = Mp[i*32 + j];
        }
        __syncthreads();
        if (tid < 32) {
            float y = 0.f;
            #pragma unroll 8
            for (int j = 0; j < 32; j++) y += mv[lane*33 + j] * sy[col0 + j];
            __syncwarp();
            if (lane < pw) sy[col0 + lane] = y;
        }
        __syncthreads();
        int rem = NEQX - col0 - pw;
        if (tid < rem) {
            int i = col0 + pw + tid;
            float s = 0.f;
            #pragma unroll 8
            for (int c = 0; c < 32; c++)
                if (c < pw) s += S[(col0 + c)*LDSM + i] * sy[col0 + c];
            sy[i] -= s;
        }
        __syncthreads();
    }
    // backward: L^T x = y
    for (int p = NPAN - 1; p >= 0; p--) {
        int col0 = p * 32;
        int pw = NEQX - col0; if (pw > 32) pw = 32;
        const float* Mp = Minv + p * 1024;
        for (int idx = tid; idx < 1024; idx += 768) {
            int i = idx >> 5, j = idx & 31;
            mv[i*33 + j] = Mp[i*32 + j];
        }
        __syncthreads();
        if (tid < 32) {
            float x = 0.f;
            #pragma unroll 8
            for (int j = 0; j < 32; j++) x += mv[j*33 + lane] * sy[col0 + j];
            __syncwarp();
            if (lane < pw) sy[col0 + lane] = x;
        }
        __syncthreads();
        if (tid < col0) {
            float s = 0.f;
            #pragma unroll 8
            for (int c = 0; c < 32; c++)
                if (c < pw) s += S[(col0 + c)*LDSM + tid] * sy[col0 + c];
            sy[tid] -= s;
        }
        __syncthreads();
    }
    // sy now holds dnu

    // step phase
    float cand = BIGV;
    float t = 0.f, dz = 0.f, ds = 0.f, dlam = 0.f, si = 0.f, li = 0.f;
    if (tid < NXX) {
        #pragma unroll 8
        for (int j = 0; j < NEQX; j++) t += A[j*NXX + tid] * sy[j];
        float r1   = g_R1 [b*NXX + tid];
        float hinv = g_HINV[b*NXX + tid];
        float rp   = g_RP [b*NXX + tid];
        float rs   = g_RS [b*NXX + tid];
        si = g_Sl[b*NXX + tid];
        li = g_Lm[b*NXX + tid];
        dz = (r1 - t) * hinv;
        ds = dz - rp;
        dlam = (-rs - li*ds) / si;
        if (ds   < 0.f) cand = fminf(cand, -si/ds);
        if (dlam < 0.f) cand = fminf(cand, -li/dlam);
    }
    float am = blkMin(cand, red);
    float alpha = fminf(1.0f, 0.99f * am);
    if (tid < NXX) {
        g_Z [b*NXX + tid] += alpha * dz;
        g_Sl[b*NXX + tid]  = si + alpha * ds;
        g_Lm[b*NXX + tid]  = li + alpha * dlam;
        g_Qt[b*NXX + tid] += alpha * t;
    }
    if (tid < NEQX) g_NU[b*NEQX + tid] += alpha * sy[tid];
}

// ---------------- init rhs: -A (p*Hinv0) - b ----------------
__global__ void __launch_bounds__(768) k_rhs0(const float* __restrict__ A, const float* __restrict__ bv) {
    int b = blockIdx.x, tid = threadIdx.x;
    __shared__ float su[NXX];
    if (tid < NXX) su[tid] = g_P[b*NXX + tid] * g_Hinv0[tid];
    __syncthreads();
    int w = tid >> 5, lane = tid & 31;
    for (int g = w; g < NEQX/4; g += 24) {
        int j = g * 4;
        const float* A0 = A + (size_t)j*NXX;
        float s0=0.f, s1=0.f, s2=0.f, s3=0.f;
        for (int k = lane; k < NXX; k += 32) {
            float u = su[k];
            s0 += A0[k]         * u;
            s1 += A0[NXX + k]   * u;
            s2 += A0[2*NXX + k] * u;
            s3 += A0[3*NXX + k] * u;
        }
        #pragma unroll
        for (int o = 16; o; o >>= 1) {
            s0 += __shfl_xor_sync(0xffffffffu, s0, o);
            s1 += __shfl_xor_sync(0xffffffffu, s1, o);
            s2 += __shfl_xor_sync(0xffffffffu, s2, o);
            s3 += __shfl_xor_sync(0xffffffffu, s3, o);
        }
        if (lane == 0) {
            g_RHS[b*NEQX + j]     = -s0 - bv[j];
            g_RHS[b*NEQX + j + 1] = -s1 - bv[j+1];
            g_RHS[b*NEQX + j + 2] = -s2 - bv[j+2];
            g_RHS[b*NEQX + j + 3] = -s3 - bv[j+3];
        }
    }
}

// ---------------- init z, s, lam, q ----------------
__global__ void __launch_bounds__(768) k_initz(const float* __restrict__ A, const float* __restrict__ h) {
    int b = blockIdx.x, tid = threadIdx.x;
    __shared__ float snu[NEQX];
    if (tid < NEQX) snu[tid] = g_NU[b*NEQX + tid];
    __syncthreads();
    if (tid < NXX) {
        float q = 0.f;
        #pragma unroll 8
        for (int j = 0; j < NEQX; j++) q += A[j*NXX + tid] * snu[j];
        float z = (-g_P[b*NXX + tid] - q) * g_Hinv0[tid];
        float s = fmaxf(h[tid] + z, 1.0f);
        g_Qt[b*NXX + tid] = q;
        g_Z [b*NXX + tid] = z;
        g_Sl[b*NXX + tid] = s;
        g_Lm[b*NXX + tid] = 1.0f;
    }
}

// ---------------- per-iteration residuals + dnu RHS ----------------
__global__ void __launch_bounds__(768) k_res(const float* __restrict__ A,
                                             const float* __restrict__ bv,
                                             const float* __restrict__ h) {
    int b = blockIdx.x, tid = threadIdx.x;
    __shared__ float su[NXX];
    __shared__ float red[32];
    float si = 0.f, li = 0.f, part = 0.f;
    if (tid < NXX) {
        si = g_Sl[b*NXX + tid];
        li = g_Lm[b*NXX + tid];
        part = si * li;
    }
    float mu = blkSum(part, red) * (1.0f / (float)NXX);
    if (tid < NXX) {
        float zi = g_Z[b*NXX + tid];
        float pi = g_P[b*NXX + tid];
        float qi = g_Qt[b*NXX + tid];
        float qd = g_Qd[tid];
        float hi = h[tid];
        float rz = qd*zi + pi - li + qi;
        float rp = si - zi - hi;
        float rs = si*li - SIGC*mu;
        float hd = qd + li/si;
        float hinv = 1.0f/hd;
        float r1 = -rz + (li*rp - rs)/si;
        g_HINV[b*NXX + tid] = hinv;
        g_R1 [b*NXX + tid] = r1;
        g_RP [b*NXX + tid] = rp;
        g_RS [b*NXX + tid] = rs;
        su[tid] = r1*hinv + zi;
    }
    __syncthreads();
    int w = tid >> 5, lane = tid & 31;
    for (int g = w; g < NEQX/4; g += 24) {
        int j = g * 4;
        const float* A0 = A + (size_t)j*NXX;
        float s0=0.f, s1=0.f, s2=0.f, s3=0.f;
        for (int k = lane; k < NXX; k += 32) {
            float u = su[k];
            s0 += A0[k]         * u;
            s1 += A0[NXX + k]   * u;
            s2 += A0[2*NXX + k] * u;
            s3 += A0[3*NXX + k] * u;
        }
        #pragma unroll
        for (int o = 16; o; o >>= 1) {
            s0 += __shfl_xor_sync(0xffffffffu, s0, o);
            s1 += __shfl_xor_sync(0xffffffffu, s1, o);
            s2 += __shfl_xor_sync(0xffffffffu, s2, o);
            s3 += __shfl_xor_sync(0xffffffffu, s3, o);
        }
        if (lane == 0) {
            g_RHS[b*NEQX + j]     = s0 - bv[j];
            g_RHS[b*NEQX + j + 1] = s1 - bv[j+1];
            g_RHS[b*NEQX + j + 2] = s2 - bv[j+2];
            g_RHS[b*NEQX + j + 3] = s3 - bv[j+3];
        }
    }
}

// ---------------- output copy ----------------
__global__ void k_out(float* __restrict__ out) {
    int b = blockIdx.x, i = threadIdx.x;
    if (i < NXX) out[b*NXX + i] = g_Z[b*NXX + i];
}

// ---------------- launch ----------------
extern "C" void kernel_launch(void* const* d_in, const int* in_sizes, int n_in,
                              void* d_out, int out_size) {
    const float* puzzles = (const float*)d_in[0];
    const float* Q       = (const float*)d_in[1];
    const float* h       = (const float*)d_in[3];
    const float* A       = (const float*)d_in[4];
    const float* bvec    = (const float*)d_in[5];
    float* out = (float*)d_out;

    // init
    k_setup  <<<BAT, 768>>>(puzzles, Q);
    k_syrk   <<<dim3(15, 1), 256>>>(A, 1);
    k_chol   <<<CLW, 256>>>(1);
    k_rhs0   <<<BAT, 768>>>(A, bvec);
    k_trsolve<<<BAT, 320>>>(1);
    k_initz  <<<BAT, 768>>>(A, h);

    // 10 PDIPM iterations
    for (int it = 0; it < 10; it++) {
        k_res      <<<BAT, 768>>>(A, bvec, h);
        k_syrk     <<<dim3(15, BAT), 256>>>(A, 0);
        k_chol     <<<BAT*CLW, 256>>>(0);
        k_stepsolve<<<BAT, 768>>>(A);
    }
    k_out<<<BAT, 768>>>(out);
}

// round 8
// speedup vs baseline: 2.1777x; 1.0515x over previous
#include <cuda_runtime.h>
#include <cuda_bf16.h>
#include <math.h>

// Problem constants
#define NXX   729
#define NEQX  300
#define BAT   16
#define LDSM  320                 // rows line-aligned: 320*4B = 10 x 128B lines
#define SSTR  (NEQX*LDSM)
#define NPAN  10
#define NB    10
#define CLW   5                   // 10 blocks / 5 CTAs = exactly 2 each
#define SIGC  0.1f
#define BIGV  1e9f

// ---------------- device scratch ----------------
__device__ float g_P   [BAT*NXX];
__device__ float g_Z   [BAT*NXX];
__device__ float g_Sl  [BAT*NXX];
__device__ float g_Lm  [BAT*NXX];
__device__ float g_Qt  [BAT*NXX];
__device__ float g_HINV[BAT*NXX];
__device__ float g_R1  [BAT*NXX];
__device__ float g_RP  [BAT*NXX];
__device__ float g_RS  [BAT*NXX];
__device__ float g_NU  [BAT*NEQX];
__device__ float g_RHS [BAT*NEQX];
__device__ float g_Smat[BAT*SSTR];
__device__ float g_S0  [SSTR];
__device__ float g_Minv[BAT*NPAN*1024];
__device__ float g_Minv0[NPAN*1024];
__device__ float g_Qd  [NXX];
__device__ float g_Hinv0[NXX];
__device__ float g_MU  [BAT];      // mu for next iteration's residuals

__device__ __forceinline__ void cluster_sync_() {
    asm volatile("barrier.cluster.arrive.aligned;" ::: "memory");
    asm volatile("barrier.cluster.wait.aligned;" ::: "memory");
}

// ---------------- reductions ----------------
__device__ __forceinline__ float blkSum(float v, float* red) {
    #pragma unroll
    for (int o = 16; o; o >>= 1) v += __shfl_xor_sync(0xffffffffu, v, o);
    int w = threadIdx.x >> 5;
    if ((threadIdx.x & 31) == 0) red[w] = v;
    __syncthreads();
    if (threadIdx.x < 32) {
        int nw = blockDim.x >> 5;
        v = (threadIdx.x < nw) ? red[threadIdx.x] : 0.f;
        #pragma unroll
        for (int o = 16; o; o >>= 1) v += __shfl_xor_sync(0xffffffffu, v, o);
        if (threadIdx.x == 0) red[0] = v;
    }
    __syncthreads();
    return red[0];
}

__device__ __forceinline__ float blkMin(float v, float* red) {
    #pragma unroll
    for (int o = 16; o; o >>= 1) v = fminf(v, __shfl_xor_sync(0xffffffffu, v, o));
    int w = threadIdx.x >> 5;
    if ((threadIdx.x & 31) == 0) red[w] = v;
    __syncthreads();
    if (threadIdx.x < 32) {
        int nw = blockDim.x >> 5;
        v = (threadIdx.x < nw) ? red[threadIdx.x] : BIGV;
        #pragma unroll
        for (int o = 16; o; o >>= 1) v = fminf(v, __shfl_xor_sync(0xffffffffu, v, o));
        if (threadIdx.x == 0) red[0] = v;
    }
    __syncthreads();
    return red[0];
}

// ---------------- setup ----------------
__global__ void k_setup(const float* __restrict__ puz, const float* __restrict__ Q) {
    int b = blockIdx.x, i = threadIdx.x;
    if (i < NXX) {
        g_P[b*NXX + i] = -puz[b*NXX + i];
        if (b == 0) {
            float qd = Q[i*NXX + i];
            g_Qd[i] = qd;
            g_Hinv0[i] = 1.0f / qd;
        }
    }
}

// ---------------- batched SYRK: S = A diag(Hinv) A^T (lower triangle) ------
__global__ void __launch_bounds__(256) k_syrk(const float* __restrict__ A, int init) {
    int t = blockIdx.x, b = blockIdx.y;
    int ti = 0;
    while ((ti + 1) * (ti + 2) / 2 <= t) ti++;
    int tj = t - ti * (ti + 1) / 2;
    const float* hv = init ? g_Hinv0 : (g_HINV + b*NXX);
    float* Sout     = init ? g_S0    : (g_Smat + b*SSTR);

    __shared__ __align__(16) float As[32*68];
    __shared__ __align__(16) float Bs[32*68];

    int tid = threadIdx.x;
    int tx = tid & 15, ty = tid >> 4;
    float acc[4][4];
    #pragma unroll
    for (int u = 0; u < 4; u++)
        #pragma unroll
        for (int v = 0; v < 4; v++) acc[u][v] = 0.f;

    int row0 = ti * 64, col0 = tj * 64;
    int cld = tid & 31, rbase = tid >> 5;

    for (int k0 = 0; k0 < NXX; k0 += 32) {
        int k = k0 + cld;
        bool kok = (k < NXX);
        float hval = kok ? hv[k] : 0.f;
        #pragma unroll
        for (int l = 0; l < 8; l++) {
            int r = rbase + l * 8;
            int gi = row0 + r;
            int gj = col0 + r;
            float av = (kok && gi < NEQX) ? A[gi*NXX + k] : 0.f;
            float bv = (kok && gj < NEQX) ? A[gj*NXX + k] : 0.f;
            As[cld*68 + r] = av * hval;
            Bs[cld*68 + r] = bv;
        }
        __syncthreads();
        #pragma unroll
        for (int kk = 0; kk < 32; kk++) {
            float4 a4 = *reinterpret_cast<const float4*>(&As[kk*68 + (ty << 2)]);
            float4 b4 = *reinterpret_cast<const float4*>(&Bs[kk*68 + (tx << 2)]);
            float av[4] = {a4.x, a4.y, a4.z, a4.w};
            float bv[4] = {b4.x, b4.y, b4.z, b4.w};
            #pragma unroll
            for (int u = 0; u < 4; u++)
                #pragma unroll
                for (int v = 0; v < 4; v++) acc[u][v] += av[u] * bv[v];
        }
        __syncthreads();
    }
    #pragma unroll
    for (int u = 0; u < 4; u++) {
        int gi = row0 + (ty << 2) + u;
        #pragma unroll
        for (int v = 0; v < 4; v++) {
            int gj = col0 + (tx << 2) + v;
            if (gi < NEQX && gj < NEQX && gj <= gi)
                Sout[gi*LDSM + gj] = acc[u][v];
        }
    }
}

// ---------------- cluster-parallel right-looking Cholesky ------------------
// CLW=5 CTAs per batch, 2 row-blocks each. Trailing update: one 32x32x32
// tile per WARP (round-robin), X_jb rows in registers, X_bi via smem
// broadcast, coalesced row read-modify-write. No intra-CTA syncs in phase E.
__global__ void __launch_bounds__(256) __cluster_dims__(CLW, 1, 1)
k_chol(int init) {
    int batch = blockIdx.x / CLW;
    unsigned crank;
    asm("mov.u32 %0, %%cluster_ctarank;" : "=r"(crank));
    float* S    = init ? g_S0    : (g_Smat + batch*SSTR);
    float* Minv = init ? g_Minv0 : (g_Minv + batch*(NPAN*1024));
    int tid = threadIdx.x;
    int lane = tid & 31;
    int wid = tid >> 5;

    __shared__ float ld[32*33];
    __shared__ float mi[32*33];
    __shared__ float sinvd[32];
    __shared__ float pan[64*33];   // own 2 blocks: staged B, then X

    for (int p = 0; p < NPAN; p++) {
        int col0 = p * 32;
        int pw = NEQX - col0; if (pw > 32) pw = 32;
        int owner = p % CLW;

        cluster_sync_();   // prior trailing updates visible everywhere

        // ---- phase A: warp0 factors diag (redundant on all CTAs);
        //      warps 1..7 stage own sub-panel rows (coalesced)
        if (wid == 0) {
            float row[32];
            #pragma unroll
            for (int j = 0; j < 32; j++)
                row[j] = (lane < pw && j < pw) ? S[(col0+lane)*LDSM + col0 + j] : 0.f;
            float sinv = 0.f;
            #pragma unroll
            for (int c = 0; c < 32; c++) {
                if (c < pw) {
                    float piv = __shfl_sync(0xffffffffu, row[c], c);
                    float inv = rsqrtf(piv);
                    float d   = piv * inv;
                    float lrc;
                    if (lane == c)      lrc = d;
                    else if (lane > c)  lrc = row[c] * inv;
                    else                lrc = 0.f;
                    row[c] = lrc;
                    if (lane == c) sinv = 1.0f / d;
                    #pragma unroll
                    for (int j = 0; j < 32; j++) {
                        if (j > c) {
                            float ljc = __shfl_sync(0xffffffffu, lrc, j);
                            row[j] -= lrc * ljc;
                        }
                    }
                }
            }
            sinvd[lane] = sinv;
            #pragma unroll
            for (int j = 0; j < 32; j++) ld[lane*33 + j] = row[j];
            if ((int)crank == owner && lane < pw) {
                #pragma unroll
                for (int j = 0; j < 32; j++)
                    S[(col0+lane)*LDSM + col0 + j] = row[j];
            }
        } else {
            #pragma unroll
            for (int s = 0; s < 2; s++) {
                int bi = (int)crank + s*CLW;
                if (bi <= p) continue;
                int nr = NEQX - bi*32; if (nr > 32) nr = 32;
                for (int idx = tid - 32; idx < 1024; idx += 224) {
                    int r = idx >> 5, c = idx & 31;
                    pan[(s*32+r)*33 + c] = (r < nr && c < pw)
                        ? S[(bi*32+r)*LDSM + col0 + c] : 0.f;
                }
            }
        }
        __syncthreads();

        // ---- phase B: warp0 computes Minv = inv(L_d) into mi ----
        if (wid == 0) {
            int c = lane;
            float xc[32];
            #pragma unroll
            for (int j = 0; j < 32; j++) xc[j] = 0.f;
            if (c < pw) xc[c] = sinvd[c];
            #pragma unroll
            for (int rr = 1; rr < 32; rr++) {
                float s = 0.f;
                #pragma unroll
                for (int j = 0; j < 32; j++)
                    if (j < rr) s += ld[rr*33 + j] * xc[j];
                if (rr > c && rr < pw && c < pw) xc[rr] = -s * sinvd[rr];
            }
            #pragma unroll
            for (int rr = 0; rr < 32; rr++) mi[rr*33 + c] = xc[rr];
            if ((int)crank == owner) {
                float* Mp = Minv + p * 1024;
                #pragma unroll
                for (int rr = 0; rr < 32; rr++) Mp[rr*32 + c] = xc[rr];
            }
        }
        __syncthreads();

        // ---- phase C: panel solve as GEMM  X = B * Minv^T ----
        #pragma unroll
        for (int s = 0; s < 2; s++) {
            int bi = (int)crank + s*CLW;
            if (bi <= p) continue;
            int r  = tid >> 3;
            int c0 = (tid & 7) << 2;
            float breg[32];
            #pragma unroll
            for (int j = 0; j < 32; j++) breg[j] = pan[(s*32+r)*33 + j];
            float a0=0.f, a1=0.f, a2=0.f, a3=0.f;
            #pragma unroll
            for (int j = 0; j < 32; j++) {
                float bj = breg[j];
                a0 += bj * mi[(c0+0)*33 + j];
                a1 += bj * mi[(c0+1)*33 + j];
                a2 += bj * mi[(c0+2)*33 + j];
                a3 += bj * mi[(c0+3)*33 + j];
            }
            __syncwarp();
            pan[(s*32+r)*33 + c0 + 0] = a0;
            pan[(s*32+r)*33 + c0 + 1] = a1;
            pan[(s*32+r)*33 + c0 + 2] = a2;
            pan[(s*32+r)*33 + c0 + 3] = a3;
        }
        __syncthreads();

        // ---- phase D: write X to gmem, lower + mirror (both coalesced) ----
        #pragma unroll
        for (int s = 0; s < 2; s++) {
            int bi = (int)crank + s*CLW;
            if (bi <= p) continue;
            int nr = NEQX - bi*32; if (nr > 32) nr = 32;
            for (int idx = tid; idx < 1024; idx += 256) {
                int r = idx >> 5, c = idx & 31;
                if (r < nr && c < pw)
                    S[(bi*32+r)*LDSM + col0 + c] = pan[(s*32+r)*33 + c];
            }
            for (int idx = tid; idx < 1024; idx += 256) {
                int c = idx >> 5, r = idx & 31;
                if (r < nr && c < pw)
                    S[(col0+c)*LDSM + bi*32 + r] = pan[(s*32+r)*33 + c];
            }
        }
        cluster_sync_();

        // ---- phase E: trailing update, one tile per warp, NO CTA syncs ----
        // out[r][c] = sum_k X_bi[r][k] * X_jb[c][k]; lane = c.
        {
            int tcount = 0;
            #pragma unroll
            for (int s = 0; s < 2; s++) {
                int bi = (int)crank + s*CLW;
                if (bi <= p) continue;
                int nri = NEQX - bi*32; if (nri > 32) nri = 32;
                for (int jb = p + 1; jb <= bi; jb++) {
                    if ((tcount++ & 7) != wid) continue;
                    int nrj = NEQX - jb*32; if (nrj > 32) nrj = 32;
                    bool cok = (lane < nrj);
                    float xjr[32];   // X_jb[lane][k] from mirror rows (coalesced)
                    #pragma unroll
                    for (int k = 0; k < 32; k++)
                        xjr[k] = cok ? S[(col0+k)*LDSM + jb*32 + lane] : 0.f;
                    for (int r = 0; r < nri; r++) {
                        float acc = 0.f;
                        #pragma unroll
                        for (int k = 0; k < 32; k++)
                            acc += pan[(s*32+r)*33 + k] * xjr[k];  // smem broadcast
                        if (cok)
                            S[(size_t)(bi*32+r)*LDSM + jb*32 + lane] -= acc; // coalesced RMW
                    }
                }
            }
        }
    }
}

// ---------------- standalone triangular solve (init only) -----------------
__global__ void __launch_bounds__(320) k_trsolve(int init) {
    int b = blockIdx.x;
    const float* S    = init ? g_S0    : (g_Smat + b*SSTR);
    const float* Minv = init ? g_Minv0 : (g_Minv + b*(NPAN*1024));
    const float* rhs  = g_RHS + b*NEQX;
    float* out        = g_NU + b*NEQX;
    __shared__ float sy[320];
    __shared__ float mv[32*33];
    int tid = threadIdx.x;
    int lane = tid & 31;
    sy[tid] = (tid < NEQX) ? rhs[tid] : 0.f;
    __syncthreads();
    for (int p = 0; p < NPAN; p++) {
        int col0 = p * 32;
        int pw = NEQX - col0; if (pw > 32) pw = 32;
        const float* Mp = Minv + p * 1024;
        for (int idx = tid; idx < 1024; idx += 320) {
            int i = idx >> 5, j = idx & 31;
            mv[i*33 + j] = Mp[i*32 + j];
        }
        __syncthreads();
        if (tid < 32) {
            float y = 0.f;
            #pragma unroll 8
            for (int j = 0; j < 32; j++) y += mv[lane*33 + j] * sy[col0 + j];
            __syncwarp();
            if (lane < pw) sy[col0 + lane] = y;
        }
        __syncthreads();
        int rem = NEQX - col0 - pw;
        if (tid < rem) {
            int i = col0 + pw + tid;
            float s = 0.f;
            #pragma unroll 8
            for (int c = 0; c < 32; c++)
                if (c < pw) s += S[(col0 + c)*LDSM + i] * sy[col0 + c];
            sy[i] -= s;
        }
        __syncthreads();
    }
    for (int p = NPAN - 1; p >= 0; p--) {
        int col0 = p * 32;
        int pw = NEQX - col0; if (pw > 32) pw = 32;
        const float* Mp = Minv + p * 1024;
        for (int idx = tid; idx < 1024; idx += 320) {
            int i = idx >> 5, j = idx & 31;
            mv[i*33 + j] = Mp[i*32 + j];
        }
        __syncthreads();
        if (tid < 32) {
            float x = 0.f;
            #pragma unroll 8
            for (int j = 0; j < 32; j++) x += mv[j*33 + lane] * sy[col0 + j];
            __syncwarp();
            if (lane < pw) sy[col0 + lane] = x;
        }
        __syncthreads();
        if (tid < col0) {
            float s = 0.f;
            #pragma unroll 8
            for (int c = 0; c < 32; c++)
                if (c < pw) s += S[(col0 + c)*LDSM + tid] * sy[col0 + c];
            sy[tid] -= s;
        }
        __syncthreads();
    }
    if (tid < NEQX) out[tid] = sy[tid];
}

// ---------------- fused trsolve + step (+ mu for next iteration) ----------
__global__ void __launch_bounds__(768) k_stepsolve(const float* __restrict__ A) {
    int b = blockIdx.x, tid = threadIdx.x, lane = tid & 31;
    const float* S    = g_Smat + b*SSTR;
    const float* Minv = g_Minv + b*(NPAN*1024);
    __shared__ float sy[320];
    __shared__ float mv[32*33];
    __shared__ float red[32];
    if (tid < 320) sy[tid] = (tid < NEQX) ? g_RHS[b*NEQX + tid] : 0.f;
    __syncthreads();

    // forward: L y = rhs
    for (int p = 0; p < NPAN; p++) {
        int col0 = p * 32;
        int pw = NEQX - col0; if (pw > 32) pw = 32;
        const float* Mp = Minv + p * 1024;
        for (int idx = tid; idx < 1024; idx += 768) {
            int i = idx >> 5, j = idx & 31;
            mv[i*33 + j] = Mp[i*32 + j];
        }
        __syncthreads();
        if (tid < 32) {
            float y = 0.f;
            #pragma unroll 8
            for (int j = 0; j < 32; j++) y += mv[lane*33 + j] * sy[col0 + j];
            __syncwarp();
            if (lane < pw) sy[col0 + lane] = y;
        }
        __syncthreads();
        int rem = NEQX - col0 - pw;
        if (tid < rem) {
            int i = col0 + pw + tid;
            float s = 0.f;
            #pragma unroll 8
            for (int c = 0; c < 32; c++)
                if (c < pw) s += S[(col0 + c)*LDSM + i] * sy[col0 + c];
            sy[i] -= s;
        }
        __syncthreads();
    }
    // backward: L^T x = y
    for (int p = NPAN - 1; p >= 0; p--) {
        int col0 = p * 32;
        int pw = NEQX - col0; if (pw > 32) pw = 32;
        const float* Mp = Minv + p * 1024;
        for (int idx = tid; idx < 1024; idx += 768) {
            int i = idx >> 5, j = idx & 31;
            mv[i*33 + j] = Mp[i*32 + j];
        }
        __syncthreads();
        if (tid < 32) {
            float x = 0.f;
            #pragma unroll 8
            for (int j = 0; j < 32; j++) x += mv[j*33 + lane] * sy[col0 + j];
            __syncwarp();
            if (lane < pw) sy[col0 + lane] = x;
        }
        __syncthreads();
        if (tid < col0) {
            float s = 0.f;
            #pragma unroll 8
            for (int c = 0; c < 32; c++)
                if (c < pw) s += S[(col0 + c)*LDSM + tid] * sy[col0 + c];
            sy[tid] -= s;
        }
        __syncthreads();
    }
    // sy now holds dnu

    // step phase
    float cand = BIGV;
    float t = 0.f, dz = 0.f, ds = 0.f, dlam = 0.f, si = 0.f, li = 0.f;
    if (tid < NXX) {
        #pragma unroll 8
        for (int j = 0; j < NEQX; j++) t += A[j*NXX + tid] * sy[j];
        float r1   = g_R1 [b*NXX + tid];
        float hinv = g_HINV[b*NXX + tid];
        float rp   = g_RP [b*NXX + tid];
        float rs   = g_RS [b*NXX + tid];
        si = g_Sl[b*NXX + tid];
        li = g_Lm[b*NXX + tid];
        dz = (r1 - t) * hinv;
        ds = dz - rp;
        dlam = (-rs - li*ds) / si;
        if (ds   < 0.f) cand = fminf(cand, -si/ds);
        if (dlam < 0.f) cand = fminf(cand, -li/dlam);
    }
    float am = blkMin(cand, red);
    float alpha = fminf(1.0f, 0.99f * am);
    float part = 0.f;
    if (tid < NXX) {
        float sn = si + alpha * ds;
        float ln = li + alpha * dlam;
        g_Z [b*NXX + tid] += alpha * dz;
        g_Sl[b*NXX + tid]  = sn;
        g_Lm[b*NXX + tid]  = ln;
        g_Qt[b*NXX + tid] += alpha * t;
        part = sn * ln;
    }
    if (tid < NEQX) g_NU[b*NEQX + tid] += alpha * sy[tid];
    float dot = blkSum(part, red);
    if (tid == 0) g_MU[b] = dot * (1.0f / (float)NXX);
}

// ---------------- init rhs: -A (p*Hinv0) - b ----------------
__global__ void __launch_bounds__(768) k_rhs0(const float* __restrict__ A, const float* __restrict__ bv) {
    int b = blockIdx.x, tid = threadIdx.x;
    __shared__ float su[NXX];
    if (tid < NXX) su[tid] = g_P[b*NXX + tid] * g_Hinv0[tid];
    __syncthreads();
    int w = tid >> 5, lane = tid & 31;
    for (int g = w; g < NEQX/4; g += 24) {
        int j = g * 4;
        const float* A0 = A + (size_t)j*NXX;
        float s0=0.f, s1=0.f, s2=0.f, s3=0.f;
        for (int k = lane; k < NXX; k += 32) {
            float u = su[k];
            s0 += A0[k]         * u;
            s1 += A0[NXX + k]   * u;
            s2 += A0[2*NXX + k] * u;
            s3 += A0[3*NXX + k] * u;
        }
        #pragma unroll
        for (int o = 16; o; o >>= 1) {
            s0 += __shfl_xor_sync(0xffffffffu, s0, o);
            s1 += __shfl_xor_sync(0xffffffffu, s1, o);
            s2 += __shfl_xor_sync(0xffffffffu, s2, o);
            s3 += __shfl_xor_sync(0xffffffffu, s3, o);
        }
        if (lane == 0) {
            g_RHS[b*NEQX + j]     = -s0 - bv[j];
            g_RHS[b*NEQX + j + 1] = -s1 - bv[j+1];
            g_RHS[b*NEQX + j + 2] = -s2 - bv[j+2];
            g_RHS[b*NEQX + j + 3] = -s3 - bv[j+3];
        }
    }
}

// ---------------- init z, s, lam, q (+ mu) ----------------
__global__ void __launch_bounds__(768) k_initz(const float* __restrict__ A, const float* __restrict__ h) {
    int b = blockIdx.x, tid = threadIdx.x;
    __shared__ float snu[NEQX];
    __shared__ float red[32];
    if (tid < NEQX) snu[tid] = g_NU[b*NEQX + tid];
    __syncthreads();
    float part = 0.f;
    if (tid < NXX) {
        float q = 0.f;
        #pragma unroll 8
        for (int j = 0; j < NEQX; j++) q += A[j*NXX + tid] * snu[j];
        float z = (-g_P[b*NXX + tid] - q) * g_Hinv0[tid];
        float s = fmaxf(h[tid] + z, 1.0f);
        g_Qt[b*NXX + tid] = q;
        g_Z [b*NXX + tid] = z;
        g_Sl[b*NXX + tid] = s;
        g_Lm[b*NXX + tid] = 1.0f;
        part = s;                       // s * lam with lam = 1
    }
    float dot = blkSum(part, red);
    if (tid == 0) g_MU[b] = dot * (1.0f / (float)NXX);
}

// ---------------- per-iteration residuals + dnu RHS (wide: 4 CTAs/batch) ---
__global__ void __launch_bounds__(768) k_res(const float* __restrict__ A,
                                             const float* __restrict__ bv,
                                             const float* __restrict__ h) {
    int x = blockIdx.x, b = blockIdx.y, tid = threadIdx.x;
    __shared__ float su[NXX];
    float mu = g_MU[b];
    if (tid < NXX) {
        float si = g_Sl[b*NXX + tid];
        float li = g_Lm[b*NXX + tid];
        float zi = g_Z[b*NXX + tid];
        float pi = g_P[b*NXX + tid];
        float qi = g_Qt[b*NXX + tid];
        float qd = g_Qd[tid];
        float hi = h[tid];
        float rz = qd*zi + pi - li + qi;
        float rp = si - zi - hi;
        float rs = si*li - SIGC*mu;
        float hd = qd + li/si;
        float hinv = 1.0f/hd;
        float r1 = -rz + (li*rp - rs)/si;
        if (x == 0) {
            g_HINV[b*NXX + tid] = hinv;
            g_R1 [b*NXX + tid] = r1;
            g_RP [b*NXX + tid] = rp;
            g_RS [b*NXX + tid] = rs;
        }
        su[tid] = r1*hinv + zi;
    }
    __syncthreads();
    int w = tid >> 5, lane = tid & 31;
    int g = x * 24 + w;                 // 4 CTAs x 24 warps = 96 slots >= 75 groups
    if (g < NEQX/4) {
        int j = g * 4;
        const float* A0 = A + (size_t)j*NXX;
        float s0=0.f, s1=0.f, s2=0.f, s3=0.f;
        for (int k = lane; k < NXX; k += 32) {
            float u = su[k];
            s0 += A0[k]         * u;
            s1 += A0[NXX + k]   * u;
            s2 += A0[2*NXX + k] * u;
            s3 += A0[3*NXX + k] * u;
        }
        #pragma unroll
        for (int o = 16; o; o >>= 1) {
            s0 += __shfl_xor_sync(0xffffffffu, s0, o);
            s1 += __shfl_xor_sync(0xffffffffu, s1, o);
            s2 += __shfl_xor_sync(0xffffffffu, s2, o);
            s3 += __shfl_xor_sync(0xffffffffu, s3, o);
        }
        if (lane == 0) {
            g_RHS[b*NEQX + j]     = s0 - bv[j];
            g_RHS[b*NEQX + j + 1] = s1 - bv[j+1];
            g_RHS[b*NEQX + j + 2] = s2 - bv[j+2];
            g_RHS[b*NEQX + j + 3] = s3 - bv[j+3];
        }
    }
}

// ---------------- output copy ----------------
__global__ void k_out(float* __restrict__ out) {
    int b = blockIdx.x, i = threadIdx.x;
    if (i < NXX) out[b*NXX + i] = g_Z[b*NXX + i];
}

// ---------------- launch ----------------
extern "C" void kernel_launch(void* const* d_in, const int* in_sizes, int n_in,
                              void* d_out, int out_size) {
    const float* puzzles = (const float*)d_in[0];
    const float* Q       = (const float*)d_in[1];
    const float* h       = (const float*)d_in[3];
    const float* A       = (const float*)d_in[4];
    const float* bvec    = (const float*)d_in[5];
    float* out = (float*)d_out;

    // init
    k_setup  <<<BAT, 768>>>(puzzles, Q);
    k_syrk   <<<dim3(15, 1), 256>>>(A, 1);
    k_chol   <<<CLW, 256>>>(1);
    k_rhs0   <<<BAT, 768>>>(A, bvec);
    k_trsolve<<<BAT, 320>>>(1);
    k_initz  <<<BAT, 768>>>(A, h);

    // 10 PDIPM iterations
    for (int it = 0; it < 10; it++) {
        k_res      <<<dim3(4, BAT), 768>>>(A, bvec, h);
        k_syrk     <<<dim3(15, BAT), 256>>>(A, 0);
        k_chol     <<<BAT*CLW, 256>>>(0);
        k_stepsolve<<<BAT, 768>>>(A);
    }
    k_out<<<BAT, 768>>>(out);
}